// round 6
// baseline (speedup 1.0000x reference)
#include <cuda_runtime.h>
#include <cstdint>
#include <stdint.h>
#include <math.h>

#define BQ 8
#define SQ 2048
#define HQ 512
#define LQ 8
#define MQ 32
#define KBQ 256
#define SPLITS 8

// ---------------- scratch (device globals, allocation-free) ----------------
__device__ float  g_h [BQ*SQ*HQ];           // hidden state [B,S,H]
__device__ float  g_y [BQ*SQ*HQ];           // GEMM scratch
__device__ float  g_xf[BQ*SQ*HQ];           // fourier branch output
__device__ float2 g_tab[MQ*SQ];             // (cos, sin) of 2*pi*m*s/S
__device__ float  g_Xrp[SPLITS*BQ*MQ*HQ];
__device__ float  g_Xip[SPLITS*BQ*MQ*HQ];
__device__ float  g_Xr[BQ*MQ*HQ];
__device__ float  g_Xi[BQ*MQ*HQ];
__device__ float  g_Yr[BQ*MQ*HQ];
__device__ float  g_Yi[BQ*MQ*HQ];
__device__ float  g_o1[BQ*SQ*(HQ/2)];
__device__ float  g_o2[BQ*SQ*(HQ/4)];
__device__ float  g_gf[BQ*HQ];
__device__ float  g_k1[BQ*HQ];

// tf32 hi/lo pre-converted operands
#define WTOT (LQ*HQ*HQ + (HQ/2)*HQ + (HQ/4)*(HQ/2))
__device__ unsigned int g_Ahi[BQ*SQ*HQ];
__device__ unsigned int g_Alo[BQ*SQ*HQ];
__device__ unsigned int g_Whi[WTOT];
__device__ unsigned int g_Wlo[WTOT];

__device__ __forceinline__ float gelu_exact(float x) {
    return 0.5f * x * (1.0f + erff(x * 0.70710678118654752440f));
}

// ---------------- tf32 helpers ----------------
__device__ __forceinline__ unsigned int f2tf32(float fval) {
    unsigned int rr;
    asm("cvt.rna.tf32.f32 %0, %1;" : "=r"(rr) : "f"(fval));
    return rr;
}

__device__ __forceinline__ void ldsm4(unsigned int& ra, unsigned int& rb,
                                      unsigned int& rc, unsigned int& rd,
                                      unsigned int addr) {
    asm volatile("ldmatrix.sync.aligned.m8n8.x4.shared.b16 {%0,%1,%2,%3}, [%4];"
                 : "=r"(ra), "=r"(rb), "=r"(rc), "=r"(rd) : "r"(addr));
}

__device__ __forceinline__ void mma_tf32(float* dacc, const unsigned int* amat,
                                         const unsigned int* bmat) {
    asm volatile(
        "mma.sync.aligned.m16n8k8.row.col.f32.tf32.tf32.f32 "
        "{%0,%1,%2,%3}, {%4,%5,%6,%7}, {%8,%9}, {%0,%1,%2,%3};"
        : "+f"(dacc[0]), "+f"(dacc[1]), "+f"(dacc[2]), "+f"(dacc[3])
        : "r"(amat[0]), "r"(amat[1]), "r"(amat[2]), "r"(amat[3]),
          "r"(bmat[0]), "r"(bmat[1]));
}

#define CPASYNC16(dstaddr, srcptr) \
    asm volatile("cp.async.cg.shared.global [%0], [%1], 16;" \
                 :: "r"(dstaddr), "l"(srcptr))
#define CPCOMMIT() asm volatile("cp.async.commit_group;")
#define CPWAIT(nn) asm volatile("cp.async.wait_group %0;" :: "n"(nn))

// ---------------- DFT twiddle tables ----------------
__global__ void k_tab() {
    int i = blockIdx.x * blockDim.x + threadIdx.x;
    if (i < MQ * SQ) {
        int m = i / SQ, s = i % SQ;
        float a = (float)(m * s) * (1.0f / 1024.0f);  // theta/pi = 2*m*s/S
        g_tab[i] = make_float2(cospif(a), sinpif(a));
    }
}

// ---------------- input projection: h = x*in_w + in_b ----------------
__global__ void k_init(const float* __restrict__ x, const float* __restrict__ in_w,
                       const float* __restrict__ in_b) {
    int i = blockIdx.x * 256 + threadIdx.x;
    if (i < BQ * SQ * HQ) {
        int c  = i & (HQ - 1);
        int bs = i >> 9;
        g_h[i] = x[bs] * in_w[c] + in_b[c];
    }
}

// ---------------- fp32 -> tf32 hi/lo split ----------------
__global__ void k_cvt(const float* __restrict__ src, unsigned int* __restrict__ dsthi,
                      unsigned int* __restrict__ dstlo, int ncount) {
    int i = blockIdx.x * 256 + threadIdx.x;
    if (i < ncount) {
        float val = src[i];
        unsigned int hpart = f2tf32(val);
        dsthi[i] = hpart;
        dstlo[i] = f2tf32(val - __uint_as_float(hpart));
    }
}

// ---------------- forward DFT (first 32 modes), split over s ----------------
__global__ void k_dftf() {
    int tid = threadIdx.x;
    int b  = blockIdx.x >> 2;
    int c  = (blockIdx.x & 3) * 128 + tid;
    int s0 = blockIdx.y * (SQ / SPLITS);
    float fr[MQ], fi[MQ];
#pragma unroll
    for (int m = 0; m < MQ; m++) { fr[m] = 0.f; fi[m] = 0.f; }
    __shared__ float2 tb[MQ * 64];
    for (int sch = 0; sch < 4; sch++) {
        int sb = s0 + sch * 64;
        __syncthreads();
        for (int i = tid; i < MQ * 64; i += 128) {
            int m = i >> 6, ss = i & 63;
            tb[i] = g_tab[m * SQ + sb + ss];
        }
        __syncthreads();
        for (int ss = 0; ss < 64; ss++) {
            float hv = g_h[(b * SQ + sb + ss) * HQ + c];
#pragma unroll
            for (int m = 0; m < MQ; m++) {
                float2 t = tb[m * 64 + ss];
                fr[m] = fmaf(hv,  t.x, fr[m]);
                fi[m] = fmaf(-hv, t.y, fi[m]);
            }
        }
    }
    int base = blockIdx.y * (BQ * MQ * HQ) + b * MQ * HQ + c;
#pragma unroll
    for (int m = 0; m < MQ; m++) {
        g_Xrp[base + m * HQ] = fr[m];
        g_Xip[base + m * HQ] = fi[m];
    }
}

__global__ void k_dftred() {
    int i = blockIdx.x * 256 + threadIdx.x;
    if (i < BQ * MQ * HQ) {
        float sr = 0.f, si = 0.f;
#pragma unroll
        for (int sp = 0; sp < SPLITS; sp++) {
            sr += g_Xrp[sp * (BQ * MQ * HQ) + i];
            si += g_Xip[sp * (BQ * MQ * HQ) + i];
        }
        g_Xr[i] = sr;
        g_Xi[i] = si;
    }
}

// ---------------- per-mode complex GEMM ----------------
__global__ void k_spec(const float* __restrict__ Wr, const float* __restrict__ Wi) {
    int m = blockIdx.x, tid = threadIdx.x;
    __shared__ float sXr[BQ][HQ];
    __shared__ float sXi[BQ][HQ];
    for (int i = tid; i < BQ * HQ; i += 128) {
        int b = i >> 9, hh = i & 511;
        sXr[b][hh] = g_Xr[(b * MQ + m) * HQ + hh];
        sXi[b][hh] = g_Xi[(b * MQ + m) * HQ + hh];
    }
    __syncthreads();
    int k = blockIdx.y * 128 + tid;
    float yr[BQ], yi[BQ];
#pragma unroll
    for (int b = 0; b < BQ; b++) { yr[b] = 0.f; yi[b] = 0.f; }
    for (int h = 0; h < HQ; h++) {
        float wr = Wr[(m * HQ + h) * HQ + k];
        float wi = Wi[(m * HQ + h) * HQ + k];
#pragma unroll
        for (int b = 0; b < BQ; b++) {
            float xr = sXr[b][h], xi = sXi[b][h];
            yr[b] = fmaf(xr, wr, fmaf(-xi, wi, yr[b]));
            yi[b] = fmaf(xr, wi, fmaf( xi, wr, yi[b]));
        }
    }
#pragma unroll
    for (int b = 0; b < BQ; b++) {
        g_Yr[(b * MQ + m) * HQ + k] = yr[b];
        g_Yi[(b * MQ + m) * HQ + k] = yi[b];
    }
}

// ---------------- inverse DFT ----------------
__global__ void k_idft() {
    int tid = threadIdx.x;
    int b = blockIdx.y >> 2;
    int c = (blockIdx.y & 3) * 128 + tid;
    float yr[MQ], yi[MQ];
#pragma unroll
    for (int m = 0; m < MQ; m++) {
        yr[m] = g_Yr[(b * MQ + m) * HQ + c];
        yi[m] = g_Yi[(b * MQ + m) * HQ + c];
    }
    __shared__ float2 tb[MQ * 64];
    int s0 = blockIdx.x * 256;
    for (int sch = 0; sch < 4; sch++) {
        int sb = s0 + sch * 64;
        __syncthreads();
        for (int i = tid; i < MQ * 64; i += 128) {
            int m = i >> 6, ss = i & 63;
            tb[i] = g_tab[m * SQ + sb + ss];
        }
        __syncthreads();
        for (int ss = 0; ss < 64; ss++) {
            float acc = 0.f;
#pragma unroll
            for (int m = 1; m < MQ; m++) {
                float2 t = tb[m * 64 + ss];
                acc = fmaf(yr[m],  t.x, acc);
                acc = fmaf(-yi[m], t.y, acc);
            }
            g_xf[(b * SQ + sb + ss) * HQ + c] = (yr[0] + 2.f * acc) * (1.0f / (float)SQ);
        }
    }
}

// ============ 3xTF32 tensor-core GEMM v2: pre-converted operands + cp.async ============
// C[M,N] = A[M,K] @ W[N,K]^T. BM=128, BN=64, BK=32, 256 threads (8 warps, 32x32 each),
// 2-stage cp.async double buffer. gmode 0: C = acc ; gmode 1: C = gelu(acc + bias[n]).
// smem per stage (words): Ahi[0..4095] Alo[4096..8191] Bhi[8192..10239] Blo[10240..12287]
#define STG_WORDS 12288

__device__ __forceinline__ void issue_slab(
    unsigned int smemBase, int stageSel,
    const unsigned int* __restrict__ Ahi, const unsigned int* __restrict__ Alo,
    const unsigned int* __restrict__ Bhi, const unsigned int* __restrict__ Blo,
    int rowBase, int colBase, int Kdim, int kpos, int tid)
{
#pragma unroll
    for (int it = 0; it < 4; it++) {
        int idx = tid + it * 256;
        int row = idx >> 3, chk = idx & 7;
        unsigned int woff = (unsigned int)(stageSel * STG_WORDS + row * 32 +
                                           ((chk ^ (row & 7)) << 2));
        size_t gsrc = (size_t)(rowBase + row) * Kdim + kpos + chk * 4;
        CPASYNC16(smemBase + woff * 4, Ahi + gsrc);
        CPASYNC16(smemBase + (woff + 4096) * 4, Alo + gsrc);
    }
#pragma unroll
    for (int it = 0; it < 2; it++) {
        int idx = tid + it * 256;
        int row = idx >> 3, chk = idx & 7;
        unsigned int woff = (unsigned int)(stageSel * STG_WORDS + 8192 + row * 32 +
                                           ((chk ^ (row & 7)) << 2));
        size_t gsrc = (size_t)(colBase + row) * Kdim + kpos + chk * 4;
        CPASYNC16(smemBase + woff * 4, Bhi + gsrc);
        CPASYNC16(smemBase + (woff + 2048) * 4, Blo + gsrc);
    }
}

__global__ void __launch_bounds__(256, 2)
k_gemm_tc2(const unsigned int* __restrict__ Ahi, const unsigned int* __restrict__ Alo,
           const unsigned int* __restrict__ Bhi, const unsigned int* __restrict__ Blo,
           float* __restrict__ Cmat, int Mdim, int Ndim, int Kdim,
           const float* __restrict__ biasPtr, int gmode) {
    extern __shared__ unsigned int shMem[];
    const int tid  = threadIdx.x;
    const int lane = tid & 31;
    const int warpIdx = tid >> 5;
    const int wmoff = (warpIdx & 3) * 32;
    const int wnoff = (warpIdx >> 2) * 32;
    const int rowBase = blockIdx.x * 128;
    const int colBase = blockIdx.y * 64;

    const unsigned int smemBase = (unsigned int)__cvta_generic_to_shared(shMem);

    const int arowA = wmoff + (lane & 15);
    const int achA  = lane >> 4;
    const int browB = wnoff + ((lane >> 4) << 3) + (lane & 7);
    const int bchB  = (lane >> 3) & 1;

    float acc[2][4][4];
#pragma unroll
    for (int fi = 0; fi < 2; fi++)
#pragma unroll
        for (int ji = 0; ji < 4; ji++)
#pragma unroll
            for (int ci = 0; ci < 4; ci++) acc[fi][ji][ci] = 0.0f;

    const int nSlab = Kdim >> 5;
    issue_slab(smemBase, 0, Ahi, Alo, Bhi, Blo, rowBase, colBase, Kdim, 0, tid);
    CPCOMMIT();

    for (int is = 0; is < nSlab; is++) {
        const int stagec = is & 1;
        if (is + 1 < nSlab) {
            issue_slab(smemBase, (is + 1) & 1, Ahi, Alo, Bhi, Blo,
                       rowBase, colBase, Kdim, (is + 1) << 5, tid);
            CPCOMMIT();
            CPWAIT(1);
        } else {
            CPWAIT(0);
        }
        __syncthreads();

        const unsigned int stW = (unsigned int)(stagec * STG_WORDS);
#pragma unroll
        for (int gi = 0; gi < 4; gi++) {
            unsigned int fragAhi[2][4];
            unsigned int fragAlo[2][4];
            unsigned int fragBhi[4][2];
            unsigned int fragBlo[4][2];
#pragma unroll
            for (int fi = 0; fi < 2; fi++) {
                int rr = arowA + fi * 16;
                int chq = 2 * gi + achA;
                unsigned int byoff = (stW + rr * 32 + ((chq ^ (rr & 7)) << 2)) << 2;
                ldsm4(fragAhi[fi][0], fragAhi[fi][1], fragAhi[fi][2], fragAhi[fi][3],
                      smemBase + byoff);
                ldsm4(fragAlo[fi][0], fragAlo[fi][1], fragAlo[fi][2], fragAlo[fi][3],
                      smemBase + byoff + 4096 * 4);
            }
#pragma unroll
            for (int pj = 0; pj < 2; pj++) {
                int rr = browB + pj * 16;
                int chq = 2 * gi + bchB;
                unsigned int byoff = (stW + 8192 + rr * 32 + ((chq ^ (rr & 7)) << 2)) << 2;
                unsigned int tqa[4];
                ldsm4(tqa[0], tqa[1], tqa[2], tqa[3], smemBase + byoff);
                fragBhi[2 * pj + 0][0] = tqa[0];
                fragBhi[2 * pj + 0][1] = tqa[1];
                fragBhi[2 * pj + 1][0] = tqa[2];
                fragBhi[2 * pj + 1][1] = tqa[3];
                unsigned int tqb[4];
                ldsm4(tqb[0], tqb[1], tqb[2], tqb[3], smemBase + byoff + 2048 * 4);
                fragBlo[2 * pj + 0][0] = tqb[0];
                fragBlo[2 * pj + 0][1] = tqb[1];
                fragBlo[2 * pj + 1][0] = tqb[2];
                fragBlo[2 * pj + 1][1] = tqb[3];
            }
#pragma unroll
            for (int fi = 0; fi < 2; fi++) {
#pragma unroll
                for (int ji = 0; ji < 4; ji++) {
                    mma_tf32(acc[fi][ji], fragAhi[fi], fragBhi[ji]);
                    mma_tf32(acc[fi][ji], fragAlo[fi], fragBhi[ji]);
                    mma_tf32(acc[fi][ji], fragAhi[fi], fragBlo[ji]);
                }
            }
        }
        __syncthreads();
    }

    // -------- epilogue --------
#pragma unroll
    for (int fi = 0; fi < 2; fi++) {
#pragma unroll
        for (int ji = 0; ji < 4; ji++) {
            int orow = rowBase + wmoff + fi * 16 + (lane >> 2);
            int ocol = colBase + wnoff + ji * 8 + (lane & 3) * 2;
            float outA = acc[fi][ji][0];
            float outB = acc[fi][ji][1];
            float outC = acc[fi][ji][2];
            float outD = acc[fi][ji][3];
            if (gmode == 1) {
                float biasLo = biasPtr[ocol];
                float biasHi = biasPtr[ocol + 1];
                outA = gelu_exact(outA + biasLo);
                outB = gelu_exact(outB + biasHi);
                outC = gelu_exact(outC + biasLo);
                outD = gelu_exact(outD + biasHi);
            }
            *(float2*)&Cmat[(size_t)orow * Ndim + ocol] = make_float2(outA, outB);
            *(float2*)&Cmat[(size_t)(orow + 8) * Ndim + ocol] = make_float2(outC, outD);
        }
    }
}

// ---------------- fused: y += conv_b + xf ; LayerNorm ; h = LN*g+b + h ----------------
__global__ void k_ln(const float* __restrict__ cb, const float* __restrict__ gg,
                     const float* __restrict__ bb) {
    int row = blockIdx.x, tid = threadIdx.x;
    float v[4], s = 0.f, s2 = 0.f;
#pragma unroll
    for (int i = 0; i < 4; i++) {
        int j = tid + i * 128;
        float t = g_y[(size_t)row * HQ + j] + g_xf[(size_t)row * HQ + j] + cb[j];
        v[i] = t; s += t; s2 += t * t;
    }
#pragma unroll
    for (int o = 16; o; o >>= 1) {
        s  += __shfl_xor_sync(0xffffffffu, s,  o);
        s2 += __shfl_xor_sync(0xffffffffu, s2, o);
    }
    __shared__ float red[64];
    int w = tid >> 5;
    if ((tid & 31) == 0) { red[w] = s; red[32 + w] = s2; }
    __syncthreads();
    float ts  = red[0] + red[1] + red[2] + red[3];
    float ts2 = red[32] + red[33] + red[34] + red[35];
    float mu  = ts * (1.f / HQ);
    float var = ts2 * (1.f / HQ) - mu * mu;
    float rinv = rsqrtf(var + 1e-5f);
#pragma unroll
    for (int i = 0; i < 4; i++) {
        int j = tid + i * 128;
        size_t idx = (size_t)row * HQ + j;
        g_h[idx] = (v[i] - mu) * rinv * gg[j] + bb[j] + g_h[idx];
    }
}

// ---------------- final projection to scalar ----------------
__global__ void k_op3(const float* __restrict__ w, const float* __restrict__ b3,
                      float* __restrict__ out) {
    int tid = threadIdx.x;
    int row = blockIdx.x * 4 + (tid >> 5);
    int lane = tid & 31;
    float s = 0.f;
#pragma unroll
    for (int i = 0; i < 4; i++) {
        int j = lane + i * 32;
        s += g_o2[(size_t)row * 128 + j] * w[j];
    }
#pragma unroll
    for (int o = 16; o; o >>= 1) s += __shfl_xor_sync(0xffffffffu, s, o);
    if (lane == 0) out[row] = s + b3[0];
}

// ---------------- mean over s ----------------
__global__ void k_mean() {
    int b = blockIdx.x >> 2;
    int c = (blockIdx.x & 3) * 128 + threadIdx.x;
    float s = 0.f;
    for (int ss = 0; ss < SQ; ss++) s += g_h[(size_t)(b * SQ + ss) * HQ + c];
    g_gf[b * HQ + c] = s * (1.f / SQ);
}

// ---------------- head: k1 = gelu(gf @ h1_w^T + h1_b) ----------------
__global__ void k_head1(const float* __restrict__ w, const float* __restrict__ bias) {
    int b = blockIdx.x, tid = threadIdx.x;
    int j = blockIdx.y * 128 + tid;
    __shared__ float sg[HQ];
    for (int i = tid; i < HQ; i += 128) sg[i] = g_gf[b * HQ + i];
    __syncthreads();
    const float4* w4 = (const float4*)(w + (size_t)j * HQ);
    float acc = 0.f;
    for (int c = 0; c < HQ / 4; c++) {
        float4 wv = w4[c];
        float4 gv = *(const float4*)&sg[c * 4];
        acc = fmaf(wv.x, gv.x, acc); acc = fmaf(wv.y, gv.y, acc);
        acc = fmaf(wv.z, gv.z, acc); acc = fmaf(wv.w, gv.w, acc);
    }
    g_k1[b * HQ + j] = gelu_exact(acc + bias[j]);
}

// ---------------- head: key_pred = sigmoid(k1 @ h2_w^T + h2_b) ----------------
__global__ void k_head2(const float* __restrict__ w, const float* __restrict__ bias,
                        float* __restrict__ out) {
    int b = blockIdx.x, tid = threadIdx.x;
    int j = blockIdx.y * 128 + tid;
    __shared__ float sk[HQ];
    for (int i = tid; i < HQ; i += 128) sk[i] = g_k1[b * HQ + i];
    __syncthreads();
    const float4* w4 = (const float4*)(w + (size_t)j * HQ);
    float acc = 0.f;
    for (int c = 0; c < HQ / 4; c++) {
        float4 wv = w4[c];
        float4 kv = *(const float4*)&sk[c * 4];
        acc = fmaf(wv.x, kv.x, acc); acc = fmaf(wv.y, kv.y, acc);
        acc = fmaf(wv.z, kv.z, acc); acc = fmaf(wv.w, kv.w, acc);
    }
    float t = acc + bias[j];
    out[BQ * SQ + b * KBQ + j] = 1.f / (1.f + expf(-t));
}

// ---------------- launch ----------------
extern "C" void kernel_launch(void* const* d_in, const int* in_sizes, int n_in,
                              void* d_out, int out_size) {
    const float* x      = (const float*)d_in[0];
    const float* in_w   = (const float*)d_in[1];
    const float* in_b   = (const float*)d_in[2];
    const float* fw_r   = (const float*)d_in[3];
    const float* fw_i   = (const float*)d_in[4];
    const float* conv_w = (const float*)d_in[5];
    const float* conv_b = (const float*)d_in[6];
    const float* ln_g   = (const float*)d_in[7];
    const float* ln_b   = (const float*)d_in[8];
    const float* op1_w  = (const float*)d_in[9];
    const float* op1_b  = (const float*)d_in[10];
    const float* op2_w  = (const float*)d_in[11];
    const float* op2_b  = (const float*)d_in[12];
    const float* op3_w  = (const float*)d_in[13];
    const float* op3_b  = (const float*)d_in[14];
    const float* h1_w   = (const float*)d_in[15];
    const float* h1_b   = (const float*)d_in[16];
    const float* h2_w   = (const float*)d_in[17];
    const float* h2_b   = (const float*)d_in[18];
    float* out = (float*)d_out;

    float *hp, *yp, *o1p, *o2p;
    unsigned int *ahip, *alop, *whip, *wlop;
    cudaGetSymbolAddress((void**)&hp,  g_h);
    cudaGetSymbolAddress((void**)&yp,  g_y);
    cudaGetSymbolAddress((void**)&o1p, g_o1);
    cudaGetSymbolAddress((void**)&o2p, g_o2);
    cudaGetSymbolAddress((void**)&ahip, g_Ahi);
    cudaGetSymbolAddress((void**)&alop, g_Alo);
    cudaGetSymbolAddress((void**)&whip, g_Whi);
    cudaGetSymbolAddress((void**)&wlop, g_Wlo);

    static int smemSet = 0;
    if (!smemSet) {
        cudaFuncSetAttribute(k_gemm_tc2, cudaFuncAttributeMaxDynamicSharedMemorySize,
                             2 * STG_WORDS * 4);
        smemSet = 1;
    }
    const int dynSmem = 2 * STG_WORDS * 4;

    const int convWCnt = LQ * HQ * HQ;
    const int op1WOff  = convWCnt;
    const int op1WCnt  = (HQ / 2) * HQ;
    const int op2WOff  = convWCnt + op1WCnt;
    const int op2WCnt  = (HQ / 4) * (HQ / 2);

    k_tab<<<(MQ * SQ + 255) / 256, 256>>>();
    k_init<<<(BQ * SQ * HQ + 255) / 256, 256>>>(x, in_w, in_b);

    // pre-convert all weights to tf32 hi/lo
    k_cvt<<<(convWCnt + 255) / 256, 256>>>(conv_w, whip, wlop, convWCnt);
    k_cvt<<<(op1WCnt + 255) / 256, 256>>>(op1_w, whip + op1WOff, wlop + op1WOff, op1WCnt);
    k_cvt<<<(op2WCnt + 255) / 256, 256>>>(op2_w, whip + op2WOff, wlop + op2WOff, op2WCnt);

    const int nElemH = BQ * SQ * HQ;
    for (int l = 0; l < LQ; l++) {
        k_dftf<<<dim3(BQ * (HQ / 128), SPLITS), 128>>>();
        k_dftred<<<(BQ * MQ * HQ + 255) / 256, 256>>>();
        k_spec<<<dim3(MQ, HQ / 128), 128>>>(fw_r + (size_t)l * MQ * HQ * HQ,
                                            fw_i + (size_t)l * MQ * HQ * HQ);
        k_idft<<<dim3(SQ / 256, BQ * 4), 128>>>();
        k_cvt<<<(nElemH + 255) / 256, 256>>>(hp, ahip, alop, nElemH);
        k_gemm_tc2<<<dim3(BQ * SQ / 128, HQ / 64), 256, dynSmem>>>(
            ahip, alop, whip + (size_t)l * HQ * HQ, wlop + (size_t)l * HQ * HQ,
            yp, BQ * SQ, HQ, HQ, (const float*)0, 0);
        k_ln<<<BQ * SQ, 128>>>(conv_b + l * HQ, ln_g + l * HQ, ln_b + l * HQ);
    }

    // output projection: H -> H/2 -> H/4 -> 1 (bias+gelu fused into epilogues)
    k_cvt<<<(nElemH + 255) / 256, 256>>>(hp, ahip, alop, nElemH);
    k_gemm_tc2<<<dim3(BQ * SQ / 128, (HQ / 2) / 64), 256, dynSmem>>>(
        ahip, alop, whip + op1WOff, wlop + op1WOff, o1p, BQ * SQ, HQ / 2, HQ, op1_b, 1);
    k_cvt<<<(BQ * SQ * (HQ / 2) + 255) / 256, 256>>>(o1p, ahip, alop, BQ * SQ * (HQ / 2));
    k_gemm_tc2<<<dim3(BQ * SQ / 128, (HQ / 4) / 64), 256, dynSmem>>>(
        ahip, alop, whip + op2WOff, wlop + op2WOff, o2p, BQ * SQ, HQ / 4, HQ / 2, op2_b, 1);
    k_op3<<<BQ * SQ / 4, 128>>>(op3_w, op3_b, out);

    // cryptanalytic head
    k_mean<<<BQ * 4, 128>>>();
    k_head1<<<dim3(BQ, HQ / 128), 128>>>(h1_w, h1_b);
    k_head2<<<dim3(BQ, KBQ / 128), 128>>>(h2_w, h2_b, out);
}

// round 7
// speedup vs baseline: 1.0072x; 1.0072x over previous
#include <cuda_runtime.h>
#include <cstdint>
#include <stdint.h>
#include <math.h>

#define BQ 8
#define SQ 2048
#define HQ 512
#define LQ 8
#define MQ 32
#define KBQ 256
#define SPLITS 8

// ---------------- scratch (device globals, allocation-free) ----------------
__device__ float  g_h [BQ*SQ*HQ];           // hidden state [B,S,H]
__device__ float  g_y [BQ*SQ*HQ];           // GEMM scratch
__device__ float  g_xf[BQ*SQ*HQ];           // fourier branch output
__device__ float2 g_tab[MQ*SQ];             // (cos, sin) of 2*pi*m*s/S
__device__ float  g_Xrp[SPLITS*BQ*MQ*HQ];
__device__ float  g_Xip[SPLITS*BQ*MQ*HQ];
__device__ float  g_Xr[BQ*MQ*HQ];
__device__ float  g_Xi[BQ*MQ*HQ];
__device__ float  g_Yr[BQ*MQ*HQ];
__device__ float  g_Yi[BQ*MQ*HQ];
__device__ float  g_o2[BQ*SQ*(HQ/4)];
__device__ float  g_gf[BQ*HQ];
__device__ float  g_k1[BQ*HQ];

// tf32 hi/lo pre-converted operands
#define WTOT (LQ*HQ*HQ + (HQ/2)*HQ + (HQ/4)*(HQ/2))
__device__ unsigned int g_Ahi[BQ*SQ*HQ];
__device__ unsigned int g_Alo[BQ*SQ*HQ];
__device__ unsigned int g_Whi[WTOT];
__device__ unsigned int g_Wlo[WTOT];
__device__ unsigned int g_o1hi[BQ*SQ*(HQ/2)];
__device__ unsigned int g_o1lo[BQ*SQ*(HQ/2)];

__device__ __forceinline__ float gelu_exact(float x) {
    return 0.5f * x * (1.0f + erff(x * 0.70710678118654752440f));
}

// ---------------- tf32 helpers ----------------
__device__ __forceinline__ unsigned int f2tf32(float fval) {
    unsigned int rr;
    asm("cvt.rna.tf32.f32 %0, %1;" : "=r"(rr) : "f"(fval));
    return rr;
}

__device__ __forceinline__ void ldsm4(unsigned int& ra, unsigned int& rb,
                                      unsigned int& rc, unsigned int& rd,
                                      unsigned int addr) {
    asm volatile("ldmatrix.sync.aligned.m8n8.x4.shared.b16 {%0,%1,%2,%3}, [%4];"
                 : "=r"(ra), "=r"(rb), "=r"(rc), "=r"(rd) : "r"(addr));
}

__device__ __forceinline__ void mma_tf32(float* dacc, const unsigned int* amat,
                                         const unsigned int* bmat) {
    asm volatile(
        "mma.sync.aligned.m16n8k8.row.col.f32.tf32.tf32.f32 "
        "{%0,%1,%2,%3}, {%4,%5,%6,%7}, {%8,%9}, {%0,%1,%2,%3};"
        : "+f"(dacc[0]), "+f"(dacc[1]), "+f"(dacc[2]), "+f"(dacc[3])
        : "r"(amat[0]), "r"(amat[1]), "r"(amat[2]), "r"(amat[3]),
          "r"(bmat[0]), "r"(bmat[1]));
}

#define CPASYNC16(dstaddr, srcptr) \
    asm volatile("cp.async.cg.shared.global [%0], [%1], 16;" \
                 :: "r"(dstaddr), "l"(srcptr))
#define CPCOMMIT() asm volatile("cp.async.commit_group;")
#define CPWAIT(nn) asm volatile("cp.async.wait_group %0;" :: "n"(nn))

// ---------------- DFT twiddle tables ----------------
__global__ void k_tab() {
    int i = blockIdx.x * blockDim.x + threadIdx.x;
    if (i < MQ * SQ) {
        int m = i / SQ, s = i % SQ;
        float a = (float)(m * s) * (1.0f / 1024.0f);
        g_tab[i] = make_float2(cospif(a), sinpif(a));
    }
}

// ---------------- input projection (fused tf32 split) ----------------
__global__ void k_init(const float* __restrict__ x, const float* __restrict__ in_w,
                       const float* __restrict__ in_b) {
    int i = blockIdx.x * 256 + threadIdx.x;
    if (i < BQ * SQ * HQ) {
        int c  = i & (HQ - 1);
        int bs = i >> 9;
        float val = x[bs] * in_w[c] + in_b[c];
        g_h[i] = val;
        unsigned int hpart = f2tf32(val);
        g_Ahi[i] = hpart;
        g_Alo[i] = f2tf32(val - __uint_as_float(hpart));
    }
}

// ---------------- fp32 -> tf32 hi/lo split (weights only, once) ----------------
__global__ void k_cvt(const float* __restrict__ src, unsigned int* __restrict__ dsthi,
                      unsigned int* __restrict__ dstlo, int ncount) {
    int i = blockIdx.x * 256 + threadIdx.x;
    if (i < ncount) {
        float val = src[i];
        unsigned int hpart = f2tf32(val);
        dsthi[i] = hpart;
        dstlo[i] = f2tf32(val - __uint_as_float(hpart));
    }
}

// ---------------- forward DFT (first 32 modes), split over s ----------------
__global__ void k_dftf() {
    int tid = threadIdx.x;
    int b  = blockIdx.x >> 2;
    int c  = (blockIdx.x & 3) * 128 + tid;
    int s0 = blockIdx.y * (SQ / SPLITS);
    float fr[MQ], fi[MQ];
#pragma unroll
    for (int m = 0; m < MQ; m++) { fr[m] = 0.f; fi[m] = 0.f; }
    __shared__ float2 tb[MQ * 64];
    for (int sch = 0; sch < 4; sch++) {
        int sb = s0 + sch * 64;
        __syncthreads();
        for (int i = tid; i < MQ * 64; i += 128) {
            int m = i >> 6, ss = i & 63;
            tb[i] = g_tab[m * SQ + sb + ss];
        }
        __syncthreads();
        for (int ss = 0; ss < 64; ss++) {
            float hv = g_h[(b * SQ + sb + ss) * HQ + c];
#pragma unroll
            for (int m = 0; m < MQ; m++) {
                float2 t = tb[m * 64 + ss];
                fr[m] = fmaf(hv,  t.x, fr[m]);
                fi[m] = fmaf(-hv, t.y, fi[m]);
            }
        }
    }
    int base = blockIdx.y * (BQ * MQ * HQ) + b * MQ * HQ + c;
#pragma unroll
    for (int m = 0; m < MQ; m++) {
        g_Xrp[base + m * HQ] = fr[m];
        g_Xip[base + m * HQ] = fi[m];
    }
}

__global__ void k_dftred() {
    int i = blockIdx.x * 256 + threadIdx.x;
    if (i < BQ * MQ * HQ) {
        float sr = 0.f, si = 0.f;
#pragma unroll
        for (int sp = 0; sp < SPLITS; sp++) {
            sr += g_Xrp[sp * (BQ * MQ * HQ) + i];
            si += g_Xip[sp * (BQ * MQ * HQ) + i];
        }
        g_Xr[i] = sr;
        g_Xi[i] = si;
    }
}

// ---------------- per-mode complex GEMM ----------------
__global__ void k_spec(const float* __restrict__ Wr, const float* __restrict__ Wi) {
    int m = blockIdx.x, tid = threadIdx.x;
    __shared__ float sXr[BQ][HQ];
    __shared__ float sXi[BQ][HQ];
    for (int i = tid; i < BQ * HQ; i += 128) {
        int b = i >> 9, hh = i & 511;
        sXr[b][hh] = g_Xr[(b * MQ + m) * HQ + hh];
        sXi[b][hh] = g_Xi[(b * MQ + m) * HQ + hh];
    }
    __syncthreads();
    int k = blockIdx.y * 128 + tid;
    float yr[BQ], yi[BQ];
#pragma unroll
    for (int b = 0; b < BQ; b++) { yr[b] = 0.f; yi[b] = 0.f; }
#pragma unroll 4
    for (int h = 0; h < HQ; h++) {
        float wr = Wr[(m * HQ + h) * HQ + k];
        float wi = Wi[(m * HQ + h) * HQ + k];
#pragma unroll
        for (int b = 0; b < BQ; b++) {
            float xr = sXr[b][h], xi = sXi[b][h];
            yr[b] = fmaf(xr, wr, fmaf(-xi, wi, yr[b]));
            yi[b] = fmaf(xr, wi, fmaf( xi, wr, yi[b]));
        }
    }
#pragma unroll
    for (int b = 0; b < BQ; b++) {
        g_Yr[(b * MQ + m) * HQ + k] = yr[b];
        g_Yi[(b * MQ + m) * HQ + k] = yi[b];
    }
}

// ---------------- inverse DFT ----------------
__global__ void k_idft() {
    int tid = threadIdx.x;
    int b = blockIdx.y >> 2;
    int c = (blockIdx.y & 3) * 128 + tid;
    float yr[MQ], yi[MQ];
#pragma unroll
    for (int m = 0; m < MQ; m++) {
        yr[m] = g_Yr[(b * MQ + m) * HQ + c];
        yi[m] = g_Yi[(b * MQ + m) * HQ + c];
    }
    __shared__ float2 tb[MQ * 64];
    int s0 = blockIdx.x * 256;
    for (int sch = 0; sch < 4; sch++) {
        int sb = s0 + sch * 64;
        __syncthreads();
        for (int i = tid; i < MQ * 64; i += 128) {
            int m = i >> 6, ss = i & 63;
            tb[i] = g_tab[m * SQ + sb + ss];
        }
        __syncthreads();
        for (int ss = 0; ss < 64; ss++) {
            float acc = 0.f;
#pragma unroll
            for (int m = 1; m < MQ; m++) {
                float2 t = tb[m * 64 + ss];
                acc = fmaf(yr[m],  t.x, acc);
                acc = fmaf(-yi[m], t.y, acc);
            }
            g_xf[(b * SQ + sb + ss) * HQ + c] = (yr[0] + 2.f * acc) * (1.0f / (float)SQ);
        }
    }
}

// ============ 3xTF32 tensor-core GEMM: pre-converted operands + cp.async ============
// C[M,N] = A[M,K] @ W[N,K]^T. BM=128, BN=64, BK=32, 256 threads, 2-stage.
// gmode 0: C=acc (float) ; 1: C=gelu(acc+bias) (float) ; 3: gelu(acc+bias) -> Chi/Clo tf32
#define STG_WORDS 12288

__device__ __forceinline__ void issue_slab(
    unsigned int smemBase, int stageSel,
    const unsigned int* __restrict__ Ahi, const unsigned int* __restrict__ Alo,
    const unsigned int* __restrict__ Bhi, const unsigned int* __restrict__ Blo,
    int rowBase, int colBase, int Kdim, int kpos, int tid)
{
#pragma unroll
    for (int it = 0; it < 4; it++) {
        int idx = tid + it * 256;
        int row = idx >> 3, chk = idx & 7;
        unsigned int woff = (unsigned int)(stageSel * STG_WORDS + row * 32 +
                                           ((chk ^ (row & 7)) << 2));
        size_t gsrc = (size_t)(rowBase + row) * Kdim + kpos + chk * 4;
        CPASYNC16(smemBase + woff * 4, Ahi + gsrc);
        CPASYNC16(smemBase + (woff + 4096) * 4, Alo + gsrc);
    }
#pragma unroll
    for (int it = 0; it < 2; it++) {
        int idx = tid + it * 256;
        int row = idx >> 3, chk = idx & 7;
        unsigned int woff = (unsigned int)(stageSel * STG_WORDS + 8192 + row * 32 +
                                           ((chk ^ (row & 7)) << 2));
        size_t gsrc = (size_t)(colBase + row) * Kdim + kpos + chk * 4;
        CPASYNC16(smemBase + woff * 4, Bhi + gsrc);
        CPASYNC16(smemBase + (woff + 2048) * 4, Blo + gsrc);
    }
}

__global__ void __launch_bounds__(256, 2)
k_gemm_tc2(const unsigned int* __restrict__ Ahi, const unsigned int* __restrict__ Alo,
           const unsigned int* __restrict__ Bhi, const unsigned int* __restrict__ Blo,
           float* __restrict__ Cmat, int Mdim, int Ndim, int Kdim,
           const float* __restrict__ biasPtr, int gmode,
           unsigned int* __restrict__ ChiPtr, unsigned int* __restrict__ CloPtr) {
    extern __shared__ unsigned int shMem[];
    const int tid  = threadIdx.x;
    const int lane = tid & 31;
    const int warpIdx = tid >> 5;
    const int wmoff = (warpIdx & 3) * 32;
    const int wnoff = (warpIdx >> 2) * 32;
    const int rowBase = blockIdx.x * 128;
    const int colBase = blockIdx.y * 64;

    const unsigned int smemBase = (unsigned int)__cvta_generic_to_shared(shMem);

    const int arowA = wmoff + (lane & 15);
    const int achA  = lane >> 4;
    const int browB = wnoff + ((lane >> 4) << 3) + (lane & 7);
    const int bchB  = (lane >> 3) & 1;

    float acc[2][4][4];
#pragma unroll
    for (int fi = 0; fi < 2; fi++)
#pragma unroll
        for (int ji = 0; ji < 4; ji++)
#pragma unroll
            for (int ci = 0; ci < 4; ci++) acc[fi][ji][ci] = 0.0f;

    const int nSlab = Kdim >> 5;
    issue_slab(smemBase, 0, Ahi, Alo, Bhi, Blo, rowBase, colBase, Kdim, 0, tid);
    CPCOMMIT();

    for (int is = 0; is < nSlab; is++) {
        const int stagec = is & 1;
        if (is + 1 < nSlab) {
            issue_slab(smemBase, (is + 1) & 1, Ahi, Alo, Bhi, Blo,
                       rowBase, colBase, Kdim, (is + 1) << 5, tid);
            CPCOMMIT();
            CPWAIT(1);
        } else {
            CPWAIT(0);
        }
        __syncthreads();

        const unsigned int stW = (unsigned int)(stagec * STG_WORDS);
#pragma unroll
        for (int gi = 0; gi < 4; gi++) {
            unsigned int fragAhi[2][4];
            unsigned int fragAlo[2][4];
            unsigned int fragBhi[4][2];
            unsigned int fragBlo[4][2];
#pragma unroll
            for (int fi = 0; fi < 2; fi++) {
                int rr = arowA + fi * 16;
                int chq = 2 * gi + achA;
                unsigned int byoff = (stW + rr * 32 + ((chq ^ (rr & 7)) << 2)) << 2;
                ldsm4(fragAhi[fi][0], fragAhi[fi][1], fragAhi[fi][2], fragAhi[fi][3],
                      smemBase + byoff);
                ldsm4(fragAlo[fi][0], fragAlo[fi][1], fragAlo[fi][2], fragAlo[fi][3],
                      smemBase + byoff + 4096 * 4);
            }
#pragma unroll
            for (int pj = 0; pj < 2; pj++) {
                int rr = browB + pj * 16;
                int chq = 2 * gi + bchB;
                unsigned int byoff = (stW + 8192 + rr * 32 + ((chq ^ (rr & 7)) << 2)) << 2;
                unsigned int tqa[4];
                ldsm4(tqa[0], tqa[1], tqa[2], tqa[3], smemBase + byoff);
                fragBhi[2 * pj + 0][0] = tqa[0];
                fragBhi[2 * pj + 0][1] = tqa[1];
                fragBhi[2 * pj + 1][0] = tqa[2];
                fragBhi[2 * pj + 1][1] = tqa[3];
                unsigned int tqb[4];
                ldsm4(tqb[0], tqb[1], tqb[2], tqb[3], smemBase + byoff + 2048 * 4);
                fragBlo[2 * pj + 0][0] = tqb[0];
                fragBlo[2 * pj + 0][1] = tqb[1];
                fragBlo[2 * pj + 1][0] = tqb[2];
                fragBlo[2 * pj + 1][1] = tqb[3];
            }
#pragma unroll
            for (int fi = 0; fi < 2; fi++) {
#pragma unroll
                for (int ji = 0; ji < 4; ji++) {
                    mma_tf32(acc[fi][ji], fragAhi[fi], fragBhi[ji]);
                    mma_tf32(acc[fi][ji], fragAlo[fi], fragBhi[ji]);
                    mma_tf32(acc[fi][ji], fragAhi[fi], fragBlo[ji]);
                }
            }
        }
        __syncthreads();
    }

    // -------- epilogue --------
#pragma unroll
    for (int fi = 0; fi < 2; fi++) {
#pragma unroll
        for (int ji = 0; ji < 4; ji++) {
            int orow = rowBase + wmoff + fi * 16 + (lane >> 2);
            int ocol = colBase + wnoff + ji * 8 + (lane & 3) * 2;
            float outA = acc[fi][ji][0];
            float outB = acc[fi][ji][1];
            float outC = acc[fi][ji][2];
            float outD = acc[fi][ji][3];
            if (gmode != 0) {
                float biasLo = biasPtr[ocol];
                float biasHi = biasPtr[ocol + 1];
                outA = gelu_exact(outA + biasLo);
                outB = gelu_exact(outB + biasHi);
                outC = gelu_exact(outC + biasLo);
                outD = gelu_exact(outD + biasHi);
            }
            if (gmode == 3) {
                uint2 hiP, loP;
                hiP.x = f2tf32(outA); loP.x = f2tf32(outA - __uint_as_float(hiP.x));
                hiP.y = f2tf32(outB); loP.y = f2tf32(outB - __uint_as_float(hiP.y));
                *(uint2*)&ChiPtr[(size_t)orow * Ndim + ocol] = hiP;
                *(uint2*)&CloPtr[(size_t)orow * Ndim + ocol] = loP;
                hiP.x = f2tf32(outC); loP.x = f2tf32(outC - __uint_as_float(hiP.x));
                hiP.y = f2tf32(outD); loP.y = f2tf32(outD - __uint_as_float(hiP.y));
                *(uint2*)&ChiPtr[(size_t)(orow + 8) * Ndim + ocol] = hiP;
                *(uint2*)&CloPtr[(size_t)(orow + 8) * Ndim + ocol] = loP;
            } else {
                *(float2*)&Cmat[(size_t)orow * Ndim + ocol] = make_float2(outA, outB);
                *(float2*)&Cmat[(size_t)(orow + 8) * Ndim + ocol] = make_float2(outC, outD);
            }
        }
    }
}

// ------ fused: y += conv_b + xf ; LayerNorm ; h = LN*g+b + h ; tf32 split of h ------
__global__ void k_ln(const float* __restrict__ cb, const float* __restrict__ gg,
                     const float* __restrict__ bb) {
    int row = blockIdx.x, tid = threadIdx.x;
    float v[4], s = 0.f, s2 = 0.f;
#pragma unroll
    for (int i = 0; i < 4; i++) {
        int j = tid + i * 128;
        float t = g_y[(size_t)row * HQ + j] + g_xf[(size_t)row * HQ + j] + cb[j];
        v[i] = t; s += t; s2 += t * t;
    }
#pragma unroll
    for (int o = 16; o; o >>= 1) {
        s  += __shfl_xor_sync(0xffffffffu, s,  o);
        s2 += __shfl_xor_sync(0xffffffffu, s2, o);
    }
    __shared__ float red[64];
    int w = tid >> 5;
    if ((tid & 31) == 0) { red[w] = s; red[32 + w] = s2; }
    __syncthreads();
    float ts  = red[0] + red[1] + red[2] + red[3];
    float ts2 = red[32] + red[33] + red[34] + red[35];
    float mu  = ts * (1.f / HQ);
    float var = ts2 * (1.f / HQ) - mu * mu;
    float rinv = rsqrtf(var + 1e-5f);
#pragma unroll
    for (int i = 0; i < 4; i++) {
        int j = tid + i * 128;
        size_t idx = (size_t)row * HQ + j;
        float hv = (v[i] - mu) * rinv * gg[j] + bb[j] + g_h[idx];
        g_h[idx] = hv;
        unsigned int hpart = f2tf32(hv);
        g_Ahi[idx] = hpart;
        g_Alo[idx] = f2tf32(hv - __uint_as_float(hpart));
    }
}

// ---------------- final projection to scalar ----------------
__global__ void k_op3(const float* __restrict__ w, const float* __restrict__ b3,
                      float* __restrict__ out) {
    int tid = threadIdx.x;
    int row = blockIdx.x * 4 + (tid >> 5);
    int lane = tid & 31;
    float s = 0.f;
#pragma unroll
    for (int i = 0; i < 4; i++) {
        int j = lane + i * 32;
        s += g_o2[(size_t)row * 128 + j] * w[j];
    }
#pragma unroll
    for (int o = 16; o; o >>= 1) s += __shfl_xor_sync(0xffffffffu, s, o);
    if (lane == 0) out[row] = s + b3[0];
}

// ---------------- mean over s (two-stage) ----------------
__global__ void k_mean1() {
    int part = blockIdx.y;
    int b = blockIdx.x >> 2;
    int c = (blockIdx.x & 3) * 128 + threadIdx.x;
    float s = 0.f;
    int sbeg = part * (SQ / 16);
    for (int ss = sbeg; ss < sbeg + (SQ / 16); ss++)
        s += g_h[(size_t)(b * SQ + ss) * HQ + c];
    g_Xrp[part * (BQ * HQ) + b * HQ + c] = s;
}

__global__ void k_mean2() {
    int i = blockIdx.x * 256 + threadIdx.x;
    if (i < BQ * HQ) {
        float s = 0.f;
#pragma unroll
        for (int part = 0; part < 16; part++) s += g_Xrp[part * (BQ * HQ) + i];
        g_gf[i] = s * (1.f / SQ);
    }
}

// ---------------- head: k1 = gelu(gf @ h1_w^T + h1_b) ----------------
__global__ void k_head1(const float* __restrict__ w, const float* __restrict__ bias) {
    int b = blockIdx.x, tid = threadIdx.x;
    int j = blockIdx.y * 128 + tid;
    __shared__ float sg[HQ];
    for (int i = tid; i < HQ; i += 128) sg[i] = g_gf[b * HQ + i];
    __syncthreads();
    const float4* w4 = (const float4*)(w + (size_t)j * HQ);
    float acc = 0.f;
    for (int c = 0; c < HQ / 4; c++) {
        float4 wv = w4[c];
        float4 gv = *(const float4*)&sg[c * 4];
        acc = fmaf(wv.x, gv.x, acc); acc = fmaf(wv.y, gv.y, acc);
        acc = fmaf(wv.z, gv.z, acc); acc = fmaf(wv.w, gv.w, acc);
    }
    g_k1[b * HQ + j] = gelu_exact(acc + bias[j]);
}

// ---------------- head: key_pred = sigmoid(k1 @ h2_w^T + h2_b) ----------------
__global__ void k_head2(const float* __restrict__ w, const float* __restrict__ bias,
                        float* __restrict__ out) {
    int b = blockIdx.x, tid = threadIdx.x;
    int j = blockIdx.y * 128 + tid;
    __shared__ float sk[HQ];
    for (int i = tid; i < HQ; i += 128) sk[i] = g_k1[b * HQ + i];
    __syncthreads();
    const float4* w4 = (const float4*)(w + (size_t)j * HQ);
    float acc = 0.f;
    for (int c = 0; c < HQ / 4; c++) {
        float4 wv = w4[c];
        float4 kv = *(const float4*)&sk[c * 4];
        acc = fmaf(wv.x, kv.x, acc); acc = fmaf(wv.y, kv.y, acc);
        acc = fmaf(wv.z, kv.z, acc); acc = fmaf(wv.w, kv.w, acc);
    }
    float t = acc + bias[j];
    out[BQ * SQ + b * KBQ + j] = 1.f / (1.f + expf(-t));
}

// ---------------- launch ----------------
extern "C" void kernel_launch(void* const* d_in, const int* in_sizes, int n_in,
                              void* d_out, int out_size) {
    const float* x      = (const float*)d_in[0];
    const float* in_w   = (const float*)d_in[1];
    const float* in_b   = (const float*)d_in[2];
    const float* fw_r   = (const float*)d_in[3];
    const float* fw_i   = (const float*)d_in[4];
    const float* conv_w = (const float*)d_in[5];
    const float* conv_b = (const float*)d_in[6];
    const float* ln_g   = (const float*)d_in[7];
    const float* ln_b   = (const float*)d_in[8];
    const float* op1_w  = (const float*)d_in[9];
    const float* op1_b  = (const float*)d_in[10];
    const float* op2_w  = (const float*)d_in[11];
    const float* op2_b  = (const float*)d_in[12];
    const float* op3_w  = (const float*)d_in[13];
    const float* op3_b  = (const float*)d_in[14];
    const float* h1_w   = (const float*)d_in[15];
    const float* h1_b   = (const float*)d_in[16];
    const float* h2_w   = (const float*)d_in[17];
    const float* h2_b   = (const float*)d_in[18];
    float* out = (float*)d_out;

    float *yp, *o2p;
    unsigned int *ahip, *alop, *whip, *wlop, *o1hip, *o1lop;
    cudaGetSymbolAddress((void**)&yp,  g_y);
    cudaGetSymbolAddress((void**)&o2p, g_o2);
    cudaGetSymbolAddress((void**)&ahip, g_Ahi);
    cudaGetSymbolAddress((void**)&alop, g_Alo);
    cudaGetSymbolAddress((void**)&whip, g_Whi);
    cudaGetSymbolAddress((void**)&wlop, g_Wlo);
    cudaGetSymbolAddress((void**)&o1hip, g_o1hi);
    cudaGetSymbolAddress((void**)&o1lop, g_o1lo);

    static int smemSet = 0;
    if (!smemSet) {
        cudaFuncSetAttribute(k_gemm_tc2, cudaFuncAttributeMaxDynamicSharedMemorySize,
                             2 * STG_WORDS * 4);
        smemSet = 1;
    }
    const int dynSmem = 2 * STG_WORDS * 4;

    const int convWCnt = LQ * HQ * HQ;
    const int op1WOff  = convWCnt;
    const int op1WCnt  = (HQ / 2) * HQ;
    const int op2WOff  = convWCnt + op1WCnt;
    const int op2WCnt  = (HQ / 4) * (HQ / 2);

    // launches 1-5 (ncu -s 5 skips these), #6 = conv GEMM layer 0
    k_tab<<<(MQ * SQ + 255) / 256, 256>>>();
    k_init<<<(BQ * SQ * HQ + 255) / 256, 256>>>(x, in_w, in_b);
    k_cvt<<<(convWCnt + 255) / 256, 256>>>(conv_w, whip, wlop, convWCnt);
    k_cvt<<<(op1WCnt + 255) / 256, 256>>>(op1_w, whip + op1WOff, wlop + op1WOff, op1WCnt);
    k_cvt<<<(op2WCnt + 255) / 256, 256>>>(op2_w, whip + op2WOff, wlop + op2WOff, op2WCnt);

    for (int l = 0; l < LQ; l++) {
        // conv branch first (depends only on h; also puts GEMM at launch #6)
        k_gemm_tc2<<<dim3(BQ * SQ / 128, HQ / 64), 256, dynSmem>>>(
            ahip, alop, whip + (size_t)l * HQ * HQ, wlop + (size_t)l * HQ * HQ,
            yp, BQ * SQ, HQ, HQ, (const float*)0, 0, (unsigned int*)0, (unsigned int*)0);
        k_dftf<<<dim3(BQ * (HQ / 128), SPLITS), 128>>>();
        k_dftred<<<(BQ * MQ * HQ + 255) / 256, 256>>>();
        k_spec<<<dim3(MQ, HQ / 128), 128>>>(fw_r + (size_t)l * MQ * HQ * HQ,
                                            fw_i + (size_t)l * MQ * HQ * HQ);
        k_idft<<<dim3(SQ / 256, BQ * 4), 128>>>();
        k_ln<<<BQ * SQ, 128>>>(conv_b + l * HQ, ln_g + l * HQ, ln_b + l * HQ);
    }

    // output projection: H -> H/2 -> H/4 -> 1
    k_gemm_tc2<<<dim3(BQ * SQ / 128, (HQ / 2) / 64), 256, dynSmem>>>(
        ahip, alop, whip + op1WOff, wlop + op1WOff, yp, BQ * SQ, HQ / 2, HQ,
        op1_b, 3, o1hip, o1lop);
    k_gemm_tc2<<<dim3(BQ * SQ / 128, (HQ / 4) / 64), 256, dynSmem>>>(
        o1hip, o1lop, whip + op2WOff, wlop + op2WOff, o2p, BQ * SQ, HQ / 4, HQ / 2,
        op2_b, 1, (unsigned int*)0, (unsigned int*)0);
    k_op3<<<BQ * SQ / 4, 128>>>(op3_w, op3_b, out);

    // cryptanalytic head
    k_mean1<<<dim3(BQ * 4, 16), 128>>>();
    k_mean2<<<(BQ * HQ + 255) / 256, 256>>>();
    k_head1<<<dim3(BQ, HQ / 128), 128>>>(h1_w, h1_b);
    k_head2<<<dim3(BQ, KBQ / 128), 128>>>(h2_w, h2_b, out);
}

// round 8
// speedup vs baseline: 1.1074x; 1.0995x over previous
#include <cuda_runtime.h>
#include <cstdint>
#include <stdint.h>
#include <math.h>

#define BQ 8
#define SQ 2048
#define HQ 512
#define LQ 8
#define MQ 32
#define KBQ 256
#define SPLITS 8

// ---------------- scratch (device globals, allocation-free) ----------------
__device__ float  g_h [BQ*SQ*HQ];           // hidden state [B,S,H]
__device__ float  g_y [BQ*SQ*HQ];           // GEMM scratch
__device__ float  g_xf[BQ*SQ*HQ];           // fourier branch output
__device__ float2 g_tab[MQ*SQ];             // (cos, sin) of 2*pi*m*s/S
__device__ float  g_Xrp[SPLITS*BQ*MQ*HQ];
__device__ float  g_Xip[SPLITS*BQ*MQ*HQ];
__device__ float  g_Xr[BQ*MQ*HQ];
__device__ float  g_Xi[BQ*MQ*HQ];
__device__ float  g_Yr[BQ*MQ*HQ];
__device__ float  g_Yi[BQ*MQ*HQ];
__device__ float  g_o2[BQ*SQ*(HQ/4)];
__device__ float  g_gf[BQ*HQ];
__device__ float  g_k1[BQ*HQ];

// bf16 hi/lo packed operands (2 bf16 per word, k-pairs)
#define WTOT (LQ*HQ*HQ + (HQ/2)*HQ + (HQ/4)*(HQ/2))
__device__ unsigned int g_A0[BQ*SQ*HQ/2];
__device__ unsigned int g_A1[BQ*SQ*HQ/2];
__device__ unsigned int g_W0[WTOT/2];
__device__ unsigned int g_W1[WTOT/2];
__device__ unsigned int g_o10[BQ*SQ*(HQ/2)/2];
__device__ unsigned int g_o11[BQ*SQ*(HQ/2)/2];

__device__ __forceinline__ float gelu_exact(float x) {
    return 0.5f * x * (1.0f + erff(x * 0.70710678118654752440f));
}

// ---------------- bf16 helpers ----------------
// pack two floats as bf16x2: element x0 -> low half, x1 -> high half
__device__ __forceinline__ unsigned int bfpack(float x0, float x1) {
    unsigned int rr;
    asm("cvt.rn.bf16x2.f32 %0, %1, %2;" : "=r"(rr) : "f"(x1), "f"(x0));
    return rr;
}

// split (x0,x1) into bf16 hi word + bf16 residual-lo word
__device__ __forceinline__ void bfsplit2(float x0, float x1,
                                         unsigned int& whi, unsigned int& wlo) {
    unsigned int hic = bfpack(x0, x1);
    float res0 = x0 - __uint_as_float(hic << 16);
    float res1 = x1 - __uint_as_float(hic & 0xffff0000u);
    whi = hic;
    wlo = bfpack(res0, res1);
}

__device__ __forceinline__ void ldsm4(unsigned int& ra, unsigned int& rb,
                                      unsigned int& rc, unsigned int& rd,
                                      unsigned int addr) {
    asm volatile("ldmatrix.sync.aligned.m8n8.x4.shared.b16 {%0,%1,%2,%3}, [%4];"
                 : "=r"(ra), "=r"(rb), "=r"(rc), "=r"(rd) : "r"(addr));
}

__device__ __forceinline__ void mma_bf16(float* dacc, const unsigned int* amat,
                                         const unsigned int* bmat) {
    asm volatile(
        "mma.sync.aligned.m16n8k16.row.col.f32.bf16.bf16.f32 "
        "{%0,%1,%2,%3}, {%4,%5,%6,%7}, {%8,%9}, {%0,%1,%2,%3};"
        : "+f"(dacc[0]), "+f"(dacc[1]), "+f"(dacc[2]), "+f"(dacc[3])
        : "r"(amat[0]), "r"(amat[1]), "r"(amat[2]), "r"(amat[3]),
          "r"(bmat[0]), "r"(bmat[1]));
}

#define CPASYNC16(dstaddr, srcptr) \
    asm volatile("cp.async.cg.shared.global [%0], [%1], 16;" \
                 :: "r"(dstaddr), "l"(srcptr))
#define CPCOMMIT() asm volatile("cp.async.commit_group;")
#define CPWAIT(nn) asm volatile("cp.async.wait_group %0;" :: "n"(nn))

// ---------------- DFT twiddle tables ----------------
__global__ void k_tab() {
    int i = blockIdx.x * blockDim.x + threadIdx.x;
    if (i < MQ * SQ) {
        int m = i / SQ, s = i % SQ;
        float a = (float)(m * s) * (1.0f / 1024.0f);
        g_tab[i] = make_float2(cospif(a), sinpif(a));
    }
}

// ---------------- input projection (fused bf16 split, pair-per-thread) ----------------
__global__ void k_init(const float* __restrict__ x, const float* __restrict__ in_w,
                       const float* __restrict__ in_b) {
    int i = blockIdx.x * 256 + threadIdx.x;      // pair index
    if (i < BQ * SQ * HQ / 2) {
        int e0 = 2 * i;
        int c0 = e0 & (HQ - 1);
        int bs = e0 >> 9;
        float xv = x[bs];
        float v0 = xv * in_w[c0] + in_b[c0];
        float v1 = xv * in_w[c0 + 1] + in_b[c0 + 1];
        g_h[e0] = v0;
        g_h[e0 + 1] = v1;
        bfsplit2(v0, v1, g_A0[i], g_A1[i]);
    }
}

// ---------------- fp32 -> bf16 hi/lo split (weights, pair-per-thread) ----------------
__global__ void k_cvt(const float* __restrict__ src, unsigned int* __restrict__ dsthi,
                      unsigned int* __restrict__ dstlo, int npairs) {
    int i = blockIdx.x * 256 + threadIdx.x;
    if (i < npairs) {
        float v0 = src[2 * i];
        float v1 = src[2 * i + 1];
        bfsplit2(v0, v1, dsthi[i], dstlo[i]);
    }
}

// ---------------- forward DFT (first 32 modes), split over s ----------------
__global__ void k_dftf() {
    int tid = threadIdx.x;
    int b  = blockIdx.x >> 2;
    int c  = (blockIdx.x & 3) * 128 + tid;
    int s0 = blockIdx.y * (SQ / SPLITS);
    float fr[MQ], fi[MQ];
#pragma unroll
    for (int m = 0; m < MQ; m++) { fr[m] = 0.f; fi[m] = 0.f; }
    __shared__ float2 tb[MQ * 64];
    for (int sch = 0; sch < 4; sch++) {
        int sb = s0 + sch * 64;
        __syncthreads();
        for (int i = tid; i < MQ * 64; i += 128) {
            int m = i >> 6, ss = i & 63;
            tb[i] = g_tab[m * SQ + sb + ss];
        }
        __syncthreads();
        for (int ss = 0; ss < 64; ss++) {
            float hv = g_h[(b * SQ + sb + ss) * HQ + c];
#pragma unroll
            for (int m = 0; m < MQ; m++) {
                float2 t = tb[m * 64 + ss];
                fr[m] = fmaf(hv,  t.x, fr[m]);
                fi[m] = fmaf(-hv, t.y, fi[m]);
            }
        }
    }
    int base = blockIdx.y * (BQ * MQ * HQ) + b * MQ * HQ + c;
#pragma unroll
    for (int m = 0; m < MQ; m++) {
        g_Xrp[base + m * HQ] = fr[m];
        g_Xip[base + m * HQ] = fi[m];
    }
}

__global__ void k_dftred() {
    int i = blockIdx.x * 256 + threadIdx.x;
    if (i < BQ * MQ * HQ) {
        float sr = 0.f, si = 0.f;
#pragma unroll
        for (int sp = 0; sp < SPLITS; sp++) {
            sr += g_Xrp[sp * (BQ * MQ * HQ) + i];
            si += g_Xip[sp * (BQ * MQ * HQ) + i];
        }
        g_Xr[i] = sr;
        g_Xi[i] = si;
    }
}

// ---------------- per-mode complex GEMM ----------------
__global__ void k_spec(const float* __restrict__ Wr, const float* __restrict__ Wi) {
    int m = blockIdx.x, tid = threadIdx.x;
    __shared__ float sXr[BQ][HQ];
    __shared__ float sXi[BQ][HQ];
    for (int i = tid; i < BQ * HQ; i += 128) {
        int b = i >> 9, hh = i & 511;
        sXr[b][hh] = g_Xr[(b * MQ + m) * HQ + hh];
        sXi[b][hh] = g_Xi[(b * MQ + m) * HQ + hh];
    }
    __syncthreads();
    int k = blockIdx.y * 128 + tid;
    float yr[BQ], yi[BQ];
#pragma unroll
    for (int b = 0; b < BQ; b++) { yr[b] = 0.f; yi[b] = 0.f; }
#pragma unroll 4
    for (int h = 0; h < HQ; h++) {
        float wr = Wr[(m * HQ + h) * HQ + k];
        float wi = Wi[(m * HQ + h) * HQ + k];
#pragma unroll
        for (int b = 0; b < BQ; b++) {
            float xr = sXr[b][h], xi = sXi[b][h];
            yr[b] = fmaf(xr, wr, fmaf(-xi, wi, yr[b]));
            yi[b] = fmaf(xr, wi, fmaf( xi, wr, yi[b]));
        }
    }
#pragma unroll
    for (int b = 0; b < BQ; b++) {
        g_Yr[(b * MQ + m) * HQ + k] = yr[b];
        g_Yi[(b * MQ + m) * HQ + k] = yi[b];
    }
}

// ---------------- inverse DFT ----------------
__global__ void k_idft() {
    int tid = threadIdx.x;
    int b = blockIdx.y >> 2;
    int c = (blockIdx.y & 3) * 128 + tid;
    float yr[MQ], yi[MQ];
#pragma unroll
    for (int m = 0; m < MQ; m++) {
        yr[m] = g_Yr[(b * MQ + m) * HQ + c];
        yi[m] = g_Yi[(b * MQ + m) * HQ + c];
    }
    __shared__ float2 tb[MQ * 64];
    int s0 = blockIdx.x * 256;
    for (int sch = 0; sch < 4; sch++) {
        int sb = s0 + sch * 64;
        __syncthreads();
        for (int i = tid; i < MQ * 64; i += 128) {
            int m = i >> 6, ss = i & 63;
            tb[i] = g_tab[m * SQ + sb + ss];
        }
        __syncthreads();
        for (int ss = 0; ss < 64; ss++) {
            float acc = 0.f;
#pragma unroll
            for (int m = 1; m < MQ; m++) {
                float2 t = tb[m * 64 + ss];
                acc = fmaf(yr[m],  t.x, acc);
                acc = fmaf(-yi[m], t.y, acc);
            }
            g_xf[(b * SQ + sb + ss) * HQ + c] = (yr[0] + 2.f * acc) * (1.0f / (float)SQ);
        }
    }
}

// ============ 3xBF16 tensor-core GEMM (hi/lo compensated) ============
// C[M,N] = A[M,K] @ W[N,K]^T. Operands packed bf16x2 (k-pairs), word row stride K/2.
// BM=128, BN=64, BK=64 bf16 elems (=32 words/row), 256 threads, 2-stage cp.async.
// gmode 0: C=acc ; 1: C=gelu(acc+bias) ; 3: gelu(acc+bias) -> packed bf16 hi/lo out
#define STG_WORDS 12288

__device__ __forceinline__ void issue_slab(
    unsigned int smemBase, int stageSel,
    const unsigned int* __restrict__ Amat0, const unsigned int* __restrict__ Amat1,
    const unsigned int* __restrict__ Bmat0, const unsigned int* __restrict__ Bmat1,
    int rowBase, int colBase, int Kw, int kw, int tid)
{
#pragma unroll
    for (int it = 0; it < 4; it++) {
        int idx = tid + it * 256;
        int row = idx >> 3, chk = idx & 7;
        unsigned int woff = (unsigned int)(stageSel * STG_WORDS + row * 32 +
                                           ((chk ^ (row & 7)) << 2));
        size_t gsrc = (size_t)(rowBase + row) * Kw + kw + chk * 4;
        CPASYNC16(smemBase + woff * 4, Amat0 + gsrc);
        CPASYNC16(smemBase + (woff + 4096) * 4, Amat1 + gsrc);
    }
#pragma unroll
    for (int it = 0; it < 2; it++) {
        int idx = tid + it * 256;
        int row = idx >> 3, chk = idx & 7;
        unsigned int woff = (unsigned int)(stageSel * STG_WORDS + 8192 + row * 32 +
                                           ((chk ^ (row & 7)) << 2));
        size_t gsrc = (size_t)(colBase + row) * Kw + kw + chk * 4;
        CPASYNC16(smemBase + woff * 4, Bmat0 + gsrc);
        CPASYNC16(smemBase + (woff + 2048) * 4, Bmat1 + gsrc);
    }
}

__global__ void __launch_bounds__(256, 2)
k_gemm_tc2(const unsigned int* __restrict__ Amat0, const unsigned int* __restrict__ Amat1,
           const unsigned int* __restrict__ Bmat0, const unsigned int* __restrict__ Bmat1,
           float* __restrict__ Cmat, int Mdim, int Ndim, int Kdim,
           const float* __restrict__ biasPtr, int gmode,
           unsigned int* __restrict__ Cout0, unsigned int* __restrict__ Cout1) {
    extern __shared__ unsigned int shMem[];
    const int tid  = threadIdx.x;
    const int lane = tid & 31;
    const int warpIdx = tid >> 5;
    const int wmoff = (warpIdx & 3) * 32;
    const int wnoff = (warpIdx >> 2) * 32;
    const int rowBase = blockIdx.x * 128;
    const int colBase = blockIdx.y * 64;
    const int Kw = Kdim >> 1;                 // words per row

    const unsigned int smemBase = (unsigned int)__cvta_generic_to_shared(shMem);

    const int arowA = wmoff + (lane & 15);
    const int achA  = lane >> 4;
    const int browB = wnoff + ((lane >> 4) << 3) + (lane & 7);
    const int bchB  = (lane >> 3) & 1;

    float acc[2][4][4];
#pragma unroll
    for (int fi = 0; fi < 2; fi++)
#pragma unroll
        for (int ji = 0; ji < 4; ji++)
#pragma unroll
            for (int ci = 0; ci < 4; ci++) acc[fi][ji][ci] = 0.0f;

    const int nSlab = Kw >> 5;                // 32 words = 64 bf16 per slab
    issue_slab(smemBase, 0, Amat0, Amat1, Bmat0, Bmat1, rowBase, colBase, Kw, 0, tid);
    CPCOMMIT();

    for (int is = 0; is < nSlab; is++) {
        const int stagec = is & 1;
        if (is + 1 < nSlab) {
            issue_slab(smemBase, (is + 1) & 1, Amat0, Amat1, Bmat0, Bmat1,
                       rowBase, colBase, Kw, (is + 1) << 5, tid);
            CPCOMMIT();
            CPWAIT(1);
        } else {
            CPWAIT(0);
        }
        __syncthreads();

        const unsigned int stW = (unsigned int)(stagec * STG_WORDS);
#pragma unroll
        for (int gi = 0; gi < 4; gi++) {       // 4 k16 groups per slab
            unsigned int fragA0[2][4];
            unsigned int fragA1[2][4];
            unsigned int fragB0[4][2];
            unsigned int fragB1[4][2];
#pragma unroll
            for (int fi = 0; fi < 2; fi++) {
                int rr = arowA + fi * 16;
                int chq = 2 * gi + achA;
                unsigned int byoff = (stW + rr * 32 + ((chq ^ (rr & 7)) << 2)) << 2;
                ldsm4(fragA0[fi][0], fragA0[fi][1], fragA0[fi][2], fragA0[fi][3],
                      smemBase + byoff);
                ldsm4(fragA1[fi][0], fragA1[fi][1], fragA1[fi][2], fragA1[fi][3],
                      smemBase + byoff + 4096 * 4);
            }
#pragma unroll
            for (int pj = 0; pj < 2; pj++) {
                int rr = browB + pj * 16;
                int chq = 2 * gi + bchB;
                unsigned int byoff = (stW + 8192 + rr * 32 + ((chq ^ (rr & 7)) << 2)) << 2;
                unsigned int tqa[4];
                ldsm4(tqa[0], tqa[1], tqa[2], tqa[3], smemBase + byoff);
                fragB0[2 * pj + 0][0] = tqa[0];
                fragB0[2 * pj + 0][1] = tqa[1];
                fragB0[2 * pj + 1][0] = tqa[2];
                fragB0[2 * pj + 1][1] = tqa[3];
                unsigned int tqb[4];
                ldsm4(tqb[0], tqb[1], tqb[2], tqb[3], smemBase + byoff + 2048 * 4);
                fragB1[2 * pj + 0][0] = tqb[0];
                fragB1[2 * pj + 0][1] = tqb[1];
                fragB1[2 * pj + 1][0] = tqb[2];
                fragB1[2 * pj + 1][1] = tqb[3];
            }
#pragma unroll
            for (int fi = 0; fi < 2; fi++) {
#pragma unroll
                for (int ji = 0; ji < 4; ji++) {
                    mma_bf16(acc[fi][ji], fragA0[fi], fragB0[ji]);
                    mma_bf16(acc[fi][ji], fragA1[fi], fragB0[ji]);
                    mma_bf16(acc[fi][ji], fragA0[fi], fragB1[ji]);
                }
            }
        }
        __syncthreads();
    }

    // -------- epilogue --------
    const int Ndw = Ndim >> 1;
#pragma unroll
    for (int fi = 0; fi < 2; fi++) {
#pragma unroll
        for (int ji = 0; ji < 4; ji++) {
            int orow = rowBase + wmoff + fi * 16 + (lane >> 2);
            int ocol = colBase + wnoff + ji * 8 + (lane & 3) * 2;
            float outA = acc[fi][ji][0];
            float outB = acc[fi][ji][1];
            float outC = acc[fi][ji][2];
            float outD = acc[fi][ji][3];
            if (gmode != 0) {
                float biasLo = biasPtr[ocol];
                float biasHi = biasPtr[ocol + 1];
                outA = gelu_exact(outA + biasLo);
                outB = gelu_exact(outB + biasHi);
                outC = gelu_exact(outC + biasLo);
                outD = gelu_exact(outD + biasHi);
            }
            if (gmode == 3) {
                size_t widx0 = (size_t)orow * Ndw + (ocol >> 1);
                size_t widx1 = (size_t)(orow + 8) * Ndw + (ocol >> 1);
                bfsplit2(outA, outB, Cout0[widx0], Cout1[widx0]);
                bfsplit2(outC, outD, Cout0[widx1], Cout1[widx1]);
            } else {
                *(float2*)&Cmat[(size_t)orow * Ndim + ocol] = make_float2(outA, outB);
                *(float2*)&Cmat[(size_t)(orow + 8) * Ndim + ocol] = make_float2(outC, outD);
            }
        }
    }
}

// ------ fused: y += conv_b + xf ; LayerNorm ; h = LN*g+b + h ; bf16 split of h ------
__global__ void k_ln(const float* __restrict__ cb, const float* __restrict__ gg,
                     const float* __restrict__ bb) {
    int row = blockIdx.x, tid = threadIdx.x;
    float v[4], s = 0.f, s2 = 0.f;
    int j0 = tid * 4;
#pragma unroll
    for (int i = 0; i < 4; i++) {
        int j = j0 + i;
        float t = g_y[(size_t)row * HQ + j] + g_xf[(size_t)row * HQ + j] + cb[j];
        v[i] = t; s += t; s2 += t * t;
    }
#pragma unroll
    for (int o = 16; o; o >>= 1) {
        s  += __shfl_xor_sync(0xffffffffu, s,  o);
        s2 += __shfl_xor_sync(0xffffffffu, s2, o);
    }
    __shared__ float red[64];
    int w = tid >> 5;
    if ((tid & 31) == 0) { red[w] = s; red[32 + w] = s2; }
    __syncthreads();
    float ts  = red[0] + red[1] + red[2] + red[3];
    float ts2 = red[32] + red[33] + red[34] + red[35];
    float mu  = ts * (1.f / HQ);
    float var = ts2 * (1.f / HQ) - mu * mu;
    float rinv = rsqrtf(var + 1e-5f);
    float hv[4];
#pragma unroll
    for (int i = 0; i < 4; i++) {
        int j = j0 + i;
        size_t idx = (size_t)row * HQ + j;
        hv[i] = (v[i] - mu) * rinv * gg[j] + bb[j] + g_h[idx];
        g_h[idx] = hv[i];
    }
    size_t wbase = (size_t)row * (HQ / 2) + tid * 2;
    bfsplit2(hv[0], hv[1], g_A0[wbase], g_A1[wbase]);
    bfsplit2(hv[2], hv[3], g_A0[wbase + 1], g_A1[wbase + 1]);
}

// ---------------- final projection to scalar ----------------
__global__ void k_op3(const float* __restrict__ w, const float* __restrict__ b3,
                      float* __restrict__ out) {
    int tid = threadIdx.x;
    int row = blockIdx.x * 4 + (tid >> 5);
    int lane = tid & 31;
    float s = 0.f;
#pragma unroll
    for (int i = 0; i < 4; i++) {
        int j = lane + i * 32;
        s += g_o2[(size_t)row * 128 + j] * w[j];
    }
#pragma unroll
    for (int o = 16; o; o >>= 1) s += __shfl_xor_sync(0xffffffffu, s, o);
    if (lane == 0) out[row] = s + b3[0];
}

// ---------------- mean over s (two-stage) ----------------
__global__ void k_mean1() {
    int part = blockIdx.y;
    int b = blockIdx.x >> 2;
    int c = (blockIdx.x & 3) * 128 + threadIdx.x;
    float s = 0.f;
    int sbeg = part * (SQ / 16);
    for (int ss = sbeg; ss < sbeg + (SQ / 16); ss++)
        s += g_h[(size_t)(b * SQ + ss) * HQ + c];
    g_Xrp[part * (BQ * HQ) + b * HQ + c] = s;
}

__global__ void k_mean2() {
    int i = blockIdx.x * 256 + threadIdx.x;
    if (i < BQ * HQ) {
        float s = 0.f;
#pragma unroll
        for (int part = 0; part < 16; part++) s += g_Xrp[part * (BQ * HQ) + i];
        g_gf[i] = s * (1.f / SQ);
    }
}

// ---------------- head: k1 = gelu(gf @ h1_w^T + h1_b) ----------------
__global__ void k_head1(const float* __restrict__ w, const float* __restrict__ bias) {
    int b = blockIdx.x, tid = threadIdx.x;
    int j = blockIdx.y * 128 + tid;
    __shared__ float sg[HQ];
    for (int i = tid; i < HQ; i += 128) sg[i] = g_gf[b * HQ + i];
    __syncthreads();
    const float4* w4 = (const float4*)(w + (size_t)j * HQ);
    float acc = 0.f;
    for (int c = 0; c < HQ / 4; c++) {
        float4 wv = w4[c];
        float4 gv = *(const float4*)&sg[c * 4];
        acc = fmaf(wv.x, gv.x, acc); acc = fmaf(wv.y, gv.y, acc);
        acc = fmaf(wv.z, gv.z, acc); acc = fmaf(wv.w, gv.w, acc);
    }
    g_k1[b * HQ + j] = gelu_exact(acc + bias[j]);
}

// ---------------- head: key_pred = sigmoid(k1 @ h2_w^T + h2_b) ----------------
__global__ void k_head2(const float* __restrict__ w, const float* __restrict__ bias,
                        float* __restrict__ out) {
    int b = blockIdx.x, tid = threadIdx.x;
    int j = blockIdx.y * 128 + tid;
    __shared__ float sk[HQ];
    for (int i = tid; i < HQ; i += 128) sk[i] = g_k1[b * HQ + i];
    __syncthreads();
    const float4* w4 = (const float4*)(w + (size_t)j * HQ);
    float acc = 0.f;
    for (int c = 0; c < HQ / 4; c++) {
        float4 wv = w4[c];
        float4 kv = *(const float4*)&sk[c * 4];
        acc = fmaf(wv.x, kv.x, acc); acc = fmaf(wv.y, kv.y, acc);
        acc = fmaf(wv.z, kv.z, acc); acc = fmaf(wv.w, kv.w, acc);
    }
    float t = acc + bias[j];
    out[BQ * SQ + b * KBQ + j] = 1.f / (1.f + expf(-t));
}

// ---------------- launch ----------------
extern "C" void kernel_launch(void* const* d_in, const int* in_sizes, int n_in,
                              void* d_out, int out_size) {
    const float* x      = (const float*)d_in[0];
    const float* in_w   = (const float*)d_in[1];
    const float* in_b   = (const float*)d_in[2];
    const float* fw_r   = (const float*)d_in[3];
    const float* fw_i   = (const float*)d_in[4];
    const float* conv_w = (const float*)d_in[5];
    const float* conv_b = (const float*)d_in[6];
    const float* ln_g   = (const float*)d_in[7];
    const float* ln_b   = (const float*)d_in[8];
    const float* op1_w  = (const float*)d_in[9];
    const float* op1_b  = (const float*)d_in[10];
    const float* op2_w  = (const float*)d_in[11];
    const float* op2_b  = (const float*)d_in[12];
    const float* op3_w  = (const float*)d_in[13];
    const float* op3_b  = (const float*)d_in[14];
    const float* h1_w   = (const float*)d_in[15];
    const float* h1_b   = (const float*)d_in[16];
    const float* h2_w   = (const float*)d_in[17];
    const float* h2_b   = (const float*)d_in[18];
    float* out = (float*)d_out;

    float *yp, *o2p;
    unsigned int *a0p, *a1p, *w0p, *w1p, *o10p, *o11p;
    cudaGetSymbolAddress((void**)&yp,  g_y);
    cudaGetSymbolAddress((void**)&o2p, g_o2);
    cudaGetSymbolAddress((void**)&a0p, g_A0);
    cudaGetSymbolAddress((void**)&a1p, g_A1);
    cudaGetSymbolAddress((void**)&w0p, g_W0);
    cudaGetSymbolAddress((void**)&w1p, g_W1);
    cudaGetSymbolAddress((void**)&o10p, g_o10);
    cudaGetSymbolAddress((void**)&o11p, g_o11);

    static int smemSet = 0;
    if (!smemSet) {
        cudaFuncSetAttribute(k_gemm_tc2, cudaFuncAttributeMaxDynamicSharedMemorySize,
                             2 * STG_WORDS * 4);
        smemSet = 1;
    }
    const int dynSmem = 2 * STG_WORDS * 4;

    // word offsets/counts (element counts / 2)
    const int convWPairs = LQ * HQ * HQ / 2;
    const int op1WOff    = convWPairs;
    const int op1WPairs  = (HQ / 2) * HQ / 2;
    const int op2WOff    = convWPairs + op1WPairs;
    const int op2WPairs  = (HQ / 4) * (HQ / 2) / 2;
    const int hPairs     = BQ * SQ * HQ / 2;

    // launch #4 = conv GEMM layer 0 (ncu -s5 -c1 lands on launch #4)
    k_tab<<<(MQ * SQ + 255) / 256, 256>>>();
    k_init<<<(hPairs + 255) / 256, 256>>>(x, in_w, in_b);
    k_cvt<<<(convWPairs + 255) / 256, 256>>>(conv_w, w0p, w1p, convWPairs);
    k_gemm_tc2<<<dim3(BQ * SQ / 128, HQ / 64), 256, dynSmem>>>(
        a0p, a1p, w0p, w1p, yp, BQ * SQ, HQ, HQ,
        (const float*)0, 0, (unsigned int*)0, (unsigned int*)0);
    k_cvt<<<(op1WPairs + 255) / 256, 256>>>(op1_w, w0p + op1WOff, w1p + op1WOff, op1WPairs);
    k_cvt<<<(op2WPairs + 255) / 256, 256>>>(op2_w, w0p + op2WOff, w1p + op2WOff, op2WPairs);

    // rest of layer 0 fourier branch + ln
    k_dftf<<<dim3(BQ * (HQ / 128), SPLITS), 128>>>();
    k_dftred<<<(BQ * MQ * HQ + 255) / 256, 256>>>();
    k_spec<<<dim3(MQ, HQ / 128), 128>>>(fw_r, fw_i);
    k_idft<<<dim3(SQ / 256, BQ * 4), 128>>>();
    k_ln<<<BQ * SQ, 128>>>(conv_b, ln_g, ln_b);

    for (int l = 1; l < LQ; l++) {
        k_gemm_tc2<<<dim3(BQ * SQ / 128, HQ / 64), 256, dynSmem>>>(
            a0p, a1p, w0p + (size_t)l * HQ * HQ / 2, w1p + (size_t)l * HQ * HQ / 2,
            yp, BQ * SQ, HQ, HQ, (const float*)0, 0, (unsigned int*)0, (unsigned int*)0);
        k_dftf<<<dim3(BQ * (HQ / 128), SPLITS), 128>>>();
        k_dftred<<<(BQ * MQ * HQ + 255) / 256, 256>>>();
        k_spec<<<dim3(MQ, HQ / 128), 128>>>(fw_r + (size_t)l * MQ * HQ * HQ,
                                            fw_i + (size_t)l * MQ * HQ * HQ);
        k_idft<<<dim3(SQ / 256, BQ * 4), 128>>>();
        k_ln<<<BQ * SQ, 128>>>(conv_b + l * HQ, ln_g + l * HQ, ln_b + l * HQ);
    }

    // output projection: H -> H/2 -> H/4 -> 1
    k_gemm_tc2<<<dim3(BQ * SQ / 128, (HQ / 2) / 64), 256, dynSmem>>>(
        a0p, a1p, w0p + op1WOff, w1p + op1WOff, yp, BQ * SQ, HQ / 2, HQ,
        op1_b, 3, o10p, o11p);
    k_gemm_tc2<<<dim3(BQ * SQ / 128, (HQ / 4) / 64), 256, dynSmem>>>(
        o10p, o11p, w0p + op2WOff, w1p + op2WOff, o2p, BQ * SQ, HQ / 4, HQ / 2,
        op2_b, 1, (unsigned int*)0, (unsigned int*)0);
    k_op3<<<BQ * SQ / 4, 128>>>(op3_w, op3_b, out);

    // cryptanalytic head
    k_mean1<<<dim3(BQ * 4, 16), 128>>>();
    k_mean2<<<(BQ * HQ + 255) / 256, 256>>>();
    k_head1<<<dim3(BQ, HQ / 128), 128>>>(h1_w, h1_b);
    k_head2<<<dim3(BQ, KBQ / 128), 128>>>(h2_w, h2_b, out);
}

// round 9
// speedup vs baseline: 1.2061x; 1.0891x over previous
#include <cuda_runtime.h>
#include <cstdint>
#include <stdint.h>
#include <math.h>

#define BQ 8
#define SQ 2048
#define HQ 512
#define LQ 8
#define MQ 32
#define KBQ 256
#define SPLITS 16

// ---------------- scratch (device globals, allocation-free) ----------------
__device__ float  g_h [BQ*SQ*HQ];           // hidden state [B,S,H]
__device__ float  g_y [BQ*SQ*HQ];           // GEMM scratch
__device__ float2 g_tab[MQ*SQ];             // (cos, sin) of 2*pi*m*s/S
__device__ float  g_Xrp[SPLITS*BQ*MQ*HQ];
__device__ float  g_Xip[SPLITS*BQ*MQ*HQ];
__device__ float  g_Xr[BQ*MQ*HQ];
__device__ float  g_Xi[BQ*MQ*HQ];
__device__ float  g_Yr[BQ*MQ*HQ];
__device__ float  g_Yi[BQ*MQ*HQ];
__device__ float  g_o2[BQ*SQ*(HQ/4)];
__device__ float  g_gf[BQ*HQ];
__device__ float  g_k1[BQ*HQ];

// bf16 hi/lo packed operands (2 bf16 per word, k-pairs)
#define WTOT (LQ*HQ*HQ + (HQ/2)*HQ + (HQ/4)*(HQ/2))
__device__ unsigned int g_A0[BQ*SQ*HQ/2];
__device__ unsigned int g_A1[BQ*SQ*HQ/2];
__device__ unsigned int g_W0[WTOT/2];
__device__ unsigned int g_W1[WTOT/2];
__device__ unsigned int g_o10[BQ*SQ*(HQ/2)/2];
__device__ unsigned int g_o11[BQ*SQ*(HQ/2)/2];

__device__ __forceinline__ float gelu_exact(float x) {
    return 0.5f * x * (1.0f + erff(x * 0.70710678118654752440f));
}

// ---------------- bf16 helpers ----------------
__device__ __forceinline__ unsigned int bfpack(float x0, float x1) {
    unsigned int rr;
    asm("cvt.rn.bf16x2.f32 %0, %1, %2;" : "=r"(rr) : "f"(x1), "f"(x0));
    return rr;
}

__device__ __forceinline__ void bfsplit2(float x0, float x1,
                                         unsigned int& whi, unsigned int& wlo) {
    unsigned int hic = bfpack(x0, x1);
    float res0 = x0 - __uint_as_float(hic << 16);
    float res1 = x1 - __uint_as_float(hic & 0xffff0000u);
    whi = hic;
    wlo = bfpack(res0, res1);
}

__device__ __forceinline__ void ldsm4(unsigned int& ra, unsigned int& rb,
                                      unsigned int& rc, unsigned int& rd,
                                      unsigned int addr) {
    asm volatile("ldmatrix.sync.aligned.m8n8.x4.shared.b16 {%0,%1,%2,%3}, [%4];"
                 : "=r"(ra), "=r"(rb), "=r"(rc), "=r"(rd) : "r"(addr));
}

__device__ __forceinline__ void mma_bf16(float* dacc, const unsigned int* amat,
                                         const unsigned int* bmat) {
    asm volatile(
        "mma.sync.aligned.m16n8k16.row.col.f32.bf16.bf16.f32 "
        "{%0,%1,%2,%3}, {%4,%5,%6,%7}, {%8,%9}, {%0,%1,%2,%3};"
        : "+f"(dacc[0]), "+f"(dacc[1]), "+f"(dacc[2]), "+f"(dacc[3])
        : "r"(amat[0]), "r"(amat[1]), "r"(amat[2]), "r"(amat[3]),
          "r"(bmat[0]), "r"(bmat[1]));
}

#define CPASYNC16(dstaddr, srcptr) \
    asm volatile("cp.async.cg.shared.global [%0], [%1], 16;" \
                 :: "r"(dstaddr), "l"(srcptr))
#define CPCOMMIT() asm volatile("cp.async.commit_group;")
#define CPWAIT(nn) asm volatile("cp.async.wait_group %0;" :: "n"(nn))

// ---------------- DFT twiddle tables ----------------
__global__ void k_tab() {
    int i = blockIdx.x * blockDim.x + threadIdx.x;
    if (i < MQ * SQ) {
        int m = i / SQ, s = i % SQ;
        float a = (float)(m * s) * (1.0f / 1024.0f);
        g_tab[i] = make_float2(cospif(a), sinpif(a));
    }
}

// ---------------- input projection (fused bf16 split, pair-per-thread) ----------------
__global__ void k_init(const float* __restrict__ x, const float* __restrict__ in_w,
                       const float* __restrict__ in_b) {
    int i = blockIdx.x * 256 + threadIdx.x;      // pair index
    if (i < BQ * SQ * HQ / 2) {
        int e0 = 2 * i;
        int c0 = e0 & (HQ - 1);
        int bs = e0 >> 9;
        float xv = x[bs];
        float v0 = xv * in_w[c0] + in_b[c0];
        float v1 = xv * in_w[c0 + 1] + in_b[c0 + 1];
        g_h[e0] = v0;
        g_h[e0 + 1] = v1;
        bfsplit2(v0, v1, g_A0[i], g_A1[i]);
    }
}

// ---------------- fp32 -> bf16 hi/lo split (weights, pair-per-thread) ----------------
__global__ void k_cvt(const float* __restrict__ src, unsigned int* __restrict__ dsthi,
                      unsigned int* __restrict__ dstlo, int npairs) {
    int i = blockIdx.x * 256 + threadIdx.x;
    if (i < npairs) {
        float v0 = src[2 * i];
        float v1 = src[2 * i + 1];
        bfsplit2(v0, v1, dsthi[i], dstlo[i]);
    }
}

// ---------------- forward DFT (first 32 modes), split over s ----------------
__global__ void k_dftf() {
    int tid = threadIdx.x;
    int b  = blockIdx.x >> 2;
    int c  = (blockIdx.x & 3) * 128 + tid;
    int s0 = blockIdx.y * (SQ / SPLITS);          // 128 s per block
    float fr[MQ], fi[MQ];
#pragma unroll
    for (int m = 0; m < MQ; m++) { fr[m] = 0.f; fi[m] = 0.f; }
    __shared__ float2 tb[MQ * 64];
    for (int sch = 0; sch < SQ / SPLITS / 64; sch++) {
        int sb = s0 + sch * 64;
        __syncthreads();
        for (int i = tid; i < MQ * 64; i += 128) {
            int m = i >> 6, ss = i & 63;
            tb[i] = g_tab[m * SQ + sb + ss];
        }
        __syncthreads();
        for (int ss = 0; ss < 64; ss++) {
            float hv = g_h[(b * SQ + sb + ss) * HQ + c];
#pragma unroll
            for (int m = 0; m < MQ; m++) {
                float2 t = tb[m * 64 + ss];
                fr[m] = fmaf(hv,  t.x, fr[m]);
                fi[m] = fmaf(-hv, t.y, fi[m]);
            }
        }
    }
    int base = blockIdx.y * (BQ * MQ * HQ) + b * MQ * HQ + c;
#pragma unroll
    for (int m = 0; m < MQ; m++) {
        g_Xrp[base + m * HQ] = fr[m];
        g_Xip[base + m * HQ] = fi[m];
    }
}

__global__ void k_dftred() {
    int i = blockIdx.x * 256 + threadIdx.x;
    if (i < BQ * MQ * HQ) {
        float sr = 0.f, si = 0.f;
#pragma unroll
        for (int sp = 0; sp < SPLITS; sp++) {
            sr += g_Xrp[sp * (BQ * MQ * HQ) + i];
            si += g_Xip[sp * (BQ * MQ * HQ) + i];
        }
        g_Xr[i] = sr;
        g_Xi[i] = si;
    }
}

// ---------------- per-mode complex GEMM ----------------
__global__ void k_spec(const float* __restrict__ Wr, const float* __restrict__ Wi) {
    int m = blockIdx.x, tid = threadIdx.x;
    __shared__ float sXr[BQ][HQ];
    __shared__ float sXi[BQ][HQ];
    for (int i = tid; i < BQ * HQ; i += 128) {
        int b = i >> 9, hh = i & 511;
        sXr[b][hh] = g_Xr[(b * MQ + m) * HQ + hh];
        sXi[b][hh] = g_Xi[(b * MQ + m) * HQ + hh];
    }
    __syncthreads();
    int k = blockIdx.y * 128 + tid;
    float yr[BQ], yi[BQ];
#pragma unroll
    for (int b = 0; b < BQ; b++) { yr[b] = 0.f; yi[b] = 0.f; }
#pragma unroll 4
    for (int h = 0; h < HQ; h++) {
        float wr = Wr[(m * HQ + h) * HQ + k];
        float wi = Wi[(m * HQ + h) * HQ + k];
#pragma unroll
        for (int b = 0; b < BQ; b++) {
            float xr = sXr[b][h], xi = sXi[b][h];
            yr[b] = fmaf(xr, wr, fmaf(-xi, wi, yr[b]));
            yi[b] = fmaf(xr, wi, fmaf( xi, wr, yi[b]));
        }
    }
#pragma unroll
    for (int b = 0; b < BQ; b++) {
        g_Yr[(b * MQ + m) * HQ + k] = yr[b];
        g_Yi[(b * MQ + m) * HQ + k] = yi[b];
    }
}

// ===== fused inverse DFT + conv-bias + LayerNorm + residual + bf16 split =====
// grid (SQ/64, BQ), block 512 (one thread per channel c)
__global__ void __launch_bounds__(512, 1)
k_idftln(const float* __restrict__ cb, const float* __restrict__ gg,
         const float* __restrict__ bb) {
    int b  = blockIdx.y;
    int s0 = blockIdx.x * 64;
    int tid = threadIdx.x;           // = channel c
    int lane = tid & 31, wrp = tid >> 5;

    float yr[MQ], yi[MQ];
#pragma unroll
    for (int m = 0; m < MQ; m++) {
        yr[m] = g_Yr[(b * MQ + m) * HQ + tid];
        yi[m] = g_Yi[(b * MQ + m) * HQ + tid];
    }
    __shared__ float2 tb[MQ * 64];
    __shared__ float red[32];
    for (int i = tid; i < MQ * 64; i += 512) {
        int m = i >> 6, ss = i & 63;
        tb[i] = g_tab[m * SQ + s0 + ss];
    }
    float gval = gg[tid], bval = bb[tid], cbv = cb[tid];
    __syncthreads();

    for (int ss = 0; ss < 64; ss++) {
        float acc = 0.f;
#pragma unroll
        for (int m = 1; m < MQ; m++) {
            float2 t = tb[m * 64 + ss];
            acc = fmaf(yr[m],  t.x, acc);
            acc = fmaf(-yi[m], t.y, acc);
        }
        float xfv = (yr[0] + 2.f * acc) * (1.0f / (float)SQ);
        size_t idx = (size_t)(b * SQ + s0 + ss) * HQ + tid;
        float tv = g_y[idx] + xfv + cbv;

        float s1 = tv, s2 = tv * tv;
#pragma unroll
        for (int o = 16; o; o >>= 1) {
            s1 += __shfl_xor_sync(0xffffffffu, s1, o);
            s2 += __shfl_xor_sync(0xffffffffu, s2, o);
        }
        if (lane == 0) { red[wrp] = s1; red[16 + wrp] = s2; }
        __syncthreads();
        float ts = 0.f, ts2 = 0.f;
#pragma unroll
        for (int q = 0; q < 16; q++) { ts += red[q]; ts2 += red[16 + q]; }
        float mu  = ts * (1.f / HQ);
        float var = ts2 * (1.f / HQ) - mu * mu;
        float rinv = rsqrtf(var + 1e-5f);

        float hv = (tv - mu) * rinv * gval + bval + g_h[idx];
        g_h[idx] = hv;
        float hOther = __shfl_xor_sync(0xffffffffu, hv, 1);
        if ((tid & 1) == 0) {
            unsigned int w0v, w1v;
            bfsplit2(hv, hOther, w0v, w1v);
            size_t widx = idx >> 1;
            g_A0[widx] = w0v;
            g_A1[widx] = w1v;
        }
        __syncthreads();
    }
}

// ============ 3xBF16 tensor-core GEMM (hi/lo compensated) ============
#define STG_WORDS 12288

__device__ __forceinline__ void issue_slab(
    unsigned int smemBase, int stageSel,
    const unsigned int* __restrict__ Amat0, const unsigned int* __restrict__ Amat1,
    const unsigned int* __restrict__ Bmat0, const unsigned int* __restrict__ Bmat1,
    int rowBase, int colBase, int Kw, int kw, int tid)
{
#pragma unroll
    for (int it = 0; it < 4; it++) {
        int idx = tid + it * 256;
        int row = idx >> 3, chk = idx & 7;
        unsigned int woff = (unsigned int)(stageSel * STG_WORDS + row * 32 +
                                           ((chk ^ (row & 7)) << 2));
        size_t gsrc = (size_t)(rowBase + row) * Kw + kw + chk * 4;
        CPASYNC16(smemBase + woff * 4, Amat0 + gsrc);
        CPASYNC16(smemBase + (woff + 4096) * 4, Amat1 + gsrc);
    }
#pragma unroll
    for (int it = 0; it < 2; it++) {
        int idx = tid + it * 256;
        int row = idx >> 3, chk = idx & 7;
        unsigned int woff = (unsigned int)(stageSel * STG_WORDS + 8192 + row * 32 +
                                           ((chk ^ (row & 7)) << 2));
        size_t gsrc = (size_t)(colBase + row) * Kw + kw + chk * 4;
        CPASYNC16(smemBase + woff * 4, Bmat0 + gsrc);
        CPASYNC16(smemBase + (woff + 2048) * 4, Bmat1 + gsrc);
    }
}

__global__ void __launch_bounds__(256, 2)
k_gemm_tc2(const unsigned int* __restrict__ Amat0, const unsigned int* __restrict__ Amat1,
           const unsigned int* __restrict__ Bmat0, const unsigned int* __restrict__ Bmat1,
           float* __restrict__ Cmat, int Mdim, int Ndim, int Kdim,
           const float* __restrict__ biasPtr, int gmode,
           unsigned int* __restrict__ Cout0, unsigned int* __restrict__ Cout1) {
    extern __shared__ unsigned int shMem[];
    const int tid  = threadIdx.x;
    const int lane = tid & 31;
    const int warpIdx = tid >> 5;
    const int wmoff = (warpIdx & 3) * 32;
    const int wnoff = (warpIdx >> 2) * 32;
    const int rowBase = blockIdx.x * 128;
    const int colBase = blockIdx.y * 64;
    const int Kw = Kdim >> 1;

    const unsigned int smemBase = (unsigned int)__cvta_generic_to_shared(shMem);

    const int arowA = wmoff + (lane & 15);
    const int achA  = lane >> 4;
    const int browB = wnoff + ((lane >> 4) << 3) + (lane & 7);
    const int bchB  = (lane >> 3) & 1;

    float acc[2][4][4];
#pragma unroll
    for (int fi = 0; fi < 2; fi++)
#pragma unroll
        for (int ji = 0; ji < 4; ji++)
#pragma unroll
            for (int ci = 0; ci < 4; ci++) acc[fi][ji][ci] = 0.0f;

    const int nSlab = Kw >> 5;
    issue_slab(smemBase, 0, Amat0, Amat1, Bmat0, Bmat1, rowBase, colBase, Kw, 0, tid);
    CPCOMMIT();

    for (int is = 0; is < nSlab; is++) {
        const int stagec = is & 1;
        if (is + 1 < nSlab) {
            issue_slab(smemBase, (is + 1) & 1, Amat0, Amat1, Bmat0, Bmat1,
                       rowBase, colBase, Kw, (is + 1) << 5, tid);
            CPCOMMIT();
            CPWAIT(1);
        } else {
            CPWAIT(0);
        }
        __syncthreads();

        const unsigned int stW = (unsigned int)(stagec * STG_WORDS);
#pragma unroll
        for (int gi = 0; gi < 4; gi++) {
            unsigned int fragA0[2][4];
            unsigned int fragA1[2][4];
            unsigned int fragB0[4][2];
            unsigned int fragB1[4][2];
#pragma unroll
            for (int fi = 0; fi < 2; fi++) {
                int rr = arowA + fi * 16;
                int chq = 2 * gi + achA;
                unsigned int byoff = (stW + rr * 32 + ((chq ^ (rr & 7)) << 2)) << 2;
                ldsm4(fragA0[fi][0], fragA0[fi][1], fragA0[fi][2], fragA0[fi][3],
                      smemBase + byoff);
                ldsm4(fragA1[fi][0], fragA1[fi][1], fragA1[fi][2], fragA1[fi][3],
                      smemBase + byoff + 4096 * 4);
            }
#pragma unroll
            for (int pj = 0; pj < 2; pj++) {
                int rr = browB + pj * 16;
                int chq = 2 * gi + bchB;
                unsigned int byoff = (stW + 8192 + rr * 32 + ((chq ^ (rr & 7)) << 2)) << 2;
                unsigned int tqa[4];
                ldsm4(tqa[0], tqa[1], tqa[2], tqa[3], smemBase + byoff);
                fragB0[2 * pj + 0][0] = tqa[0];
                fragB0[2 * pj + 0][1] = tqa[1];
                fragB0[2 * pj + 1][0] = tqa[2];
                fragB0[2 * pj + 1][1] = tqa[3];
                unsigned int tqb[4];
                ldsm4(tqb[0], tqb[1], tqb[2], tqb[3], smemBase + byoff + 2048 * 4);
                fragB1[2 * pj + 0][0] = tqb[0];
                fragB1[2 * pj + 0][1] = tqb[1];
                fragB1[2 * pj + 1][0] = tqb[2];
                fragB1[2 * pj + 1][1] = tqb[3];
            }
#pragma unroll
            for (int fi = 0; fi < 2; fi++) {
#pragma unroll
                for (int ji = 0; ji < 4; ji++) {
                    mma_bf16(acc[fi][ji], fragA0[fi], fragB0[ji]);
                    mma_bf16(acc[fi][ji], fragA1[fi], fragB0[ji]);
                    mma_bf16(acc[fi][ji], fragA0[fi], fragB1[ji]);
                }
            }
        }
        __syncthreads();
    }

    const int Ndw = Ndim >> 1;
#pragma unroll
    for (int fi = 0; fi < 2; fi++) {
#pragma unroll
        for (int ji = 0; ji < 4; ji++) {
            int orow = rowBase + wmoff + fi * 16 + (lane >> 2);
            int ocol = colBase + wnoff + ji * 8 + (lane & 3) * 2;
            float outA = acc[fi][ji][0];
            float outB = acc[fi][ji][1];
            float outC = acc[fi][ji][2];
            float outD = acc[fi][ji][3];
            if (gmode != 0) {
                float biasLo = biasPtr[ocol];
                float biasHi = biasPtr[ocol + 1];
                outA = gelu_exact(outA + biasLo);
                outB = gelu_exact(outB + biasHi);
                outC = gelu_exact(outC + biasLo);
                outD = gelu_exact(outD + biasHi);
            }
            if (gmode == 3) {
                size_t widx0 = (size_t)orow * Ndw + (ocol >> 1);
                size_t widx1 = (size_t)(orow + 8) * Ndw + (ocol >> 1);
                bfsplit2(outA, outB, Cout0[widx0], Cout1[widx0]);
                bfsplit2(outC, outD, Cout0[widx1], Cout1[widx1]);
            } else {
                *(float2*)&Cmat[(size_t)orow * Ndim + ocol] = make_float2(outA, outB);
                *(float2*)&Cmat[(size_t)(orow + 8) * Ndim + ocol] = make_float2(outC, outD);
            }
        }
    }
}

// ---------------- final projection to scalar ----------------
__global__ void k_op3(const float* __restrict__ w, const float* __restrict__ b3,
                      float* __restrict__ out) {
    int tid = threadIdx.x;
    int row = blockIdx.x * 4 + (tid >> 5);
    int lane = tid & 31;
    float s = 0.f;
#pragma unroll
    for (int i = 0; i < 4; i++) {
        int j = lane + i * 32;
        s += g_o2[(size_t)row * 128 + j] * w[j];
    }
#pragma unroll
    for (int o = 16; o; o >>= 1) s += __shfl_xor_sync(0xffffffffu, s, o);
    if (lane == 0) out[row] = s + b3[0];
}

// ---------------- mean over s (two-stage) ----------------
__global__ void k_mean1() {
    int part = blockIdx.y;
    int b = blockIdx.x >> 2;
    int c = (blockIdx.x & 3) * 128 + threadIdx.x;
    float s = 0.f;
    int sbeg = part * (SQ / 16);
    for (int ss = sbeg; ss < sbeg + (SQ / 16); ss++)
        s += g_h[(size_t)(b * SQ + ss) * HQ + c];
    g_Xrp[part * (BQ * HQ) + b * HQ + c] = s;
}

__global__ void k_mean2() {
    int i = blockIdx.x * 256 + threadIdx.x;
    if (i < BQ * HQ) {
        float s = 0.f;
#pragma unroll
        for (int part = 0; part < 16; part++) s += g_Xrp[part * (BQ * HQ) + i];
        g_gf[i] = s * (1.f / SQ);
    }
}

// ---------------- head: k1 = gelu(gf @ h1_w^T + h1_b) ----------------
__global__ void k_head1(const float* __restrict__ w, const float* __restrict__ bias) {
    int b = blockIdx.x, tid = threadIdx.x;
    int j = blockIdx.y * 128 + tid;
    __shared__ float sg[HQ];
    for (int i = tid; i < HQ; i += 128) sg[i] = g_gf[b * HQ + i];
    __syncthreads();
    const float4* w4 = (const float4*)(w + (size_t)j * HQ);
    float acc = 0.f;
    for (int c = 0; c < HQ / 4; c++) {
        float4 wv = w4[c];
        float4 gv = *(const float4*)&sg[c * 4];
        acc = fmaf(wv.x, gv.x, acc); acc = fmaf(wv.y, gv.y, acc);
        acc = fmaf(wv.z, gv.z, acc); acc = fmaf(wv.w, gv.w, acc);
    }
    g_k1[b * HQ + j] = gelu_exact(acc + bias[j]);
}

// ---------------- head: key_pred = sigmoid(k1 @ h2_w^T + h2_b) ----------------
__global__ void k_head2(const float* __restrict__ w, const float* __restrict__ bias,
                        float* __restrict__ out) {
    int b = blockIdx.x, tid = threadIdx.x;
    int j = blockIdx.y * 128 + tid;
    __shared__ float sk[HQ];
    for (int i = tid; i < HQ; i += 128) sk[i] = g_k1[b * HQ + i];
    __syncthreads();
    const float4* w4 = (const float4*)(w + (size_t)j * HQ);
    float acc = 0.f;
    for (int c = 0; c < HQ / 4; c++) {
        float4 wv = w4[c];
        float4 kv = *(const float4*)&sk[c * 4];
        acc = fmaf(wv.x, kv.x, acc); acc = fmaf(wv.y, kv.y, acc);
        acc = fmaf(wv.z, kv.z, acc); acc = fmaf(wv.w, kv.w, acc);
    }
    float t = acc + bias[j];
    out[BQ * SQ + b * KBQ + j] = 1.f / (1.f + expf(-t));
}

// ---------------- launch ----------------
extern "C" void kernel_launch(void* const* d_in, const int* in_sizes, int n_in,
                              void* d_out, int out_size) {
    const float* x      = (const float*)d_in[0];
    const float* in_w   = (const float*)d_in[1];
    const float* in_b   = (const float*)d_in[2];
    const float* fw_r   = (const float*)d_in[3];
    const float* fw_i   = (const float*)d_in[4];
    const float* conv_w = (const float*)d_in[5];
    const float* conv_b = (const float*)d_in[6];
    const float* ln_g   = (const float*)d_in[7];
    const float* ln_b   = (const float*)d_in[8];
    const float* op1_w  = (const float*)d_in[9];
    const float* op1_b  = (const float*)d_in[10];
    const float* op2_w  = (const float*)d_in[11];
    const float* op2_b  = (const float*)d_in[12];
    const float* op3_w  = (const float*)d_in[13];
    const float* op3_b  = (const float*)d_in[14];
    const float* h1_w   = (const float*)d_in[15];
    const float* h1_b   = (const float*)d_in[16];
    const float* h2_w   = (const float*)d_in[17];
    const float* h2_b   = (const float*)d_in[18];
    float* out = (float*)d_out;

    float *yp, *o2p;
    unsigned int *a0p, *a1p, *w0p, *w1p, *o10p, *o11p;
    cudaGetSymbolAddress((void**)&yp,  g_y);
    cudaGetSymbolAddress((void**)&o2p, g_o2);
    cudaGetSymbolAddress((void**)&a0p, g_A0);
    cudaGetSymbolAddress((void**)&a1p, g_A1);
    cudaGetSymbolAddress((void**)&w0p, g_W0);
    cudaGetSymbolAddress((void**)&w1p, g_W1);
    cudaGetSymbolAddress((void**)&o10p, g_o10);
    cudaGetSymbolAddress((void**)&o11p, g_o11);

    static int smemSet = 0;
    if (!smemSet) {
        cudaFuncSetAttribute(k_gemm_tc2, cudaFuncAttributeMaxDynamicSharedMemorySize,
                             2 * STG_WORDS * 4);
        smemSet = 1;
    }
    const int dynSmem = 2 * STG_WORDS * 4;

    const int convWPairs = LQ * HQ * HQ / 2;
    const int op1WOff    = convWPairs;
    const int op1WPairs  = (HQ / 2) * HQ / 2;
    const int op2WOff    = convWPairs + op1WPairs;
    const int op2WPairs  = (HQ / 4) * (HQ / 2) / 2;
    const int hPairs     = BQ * SQ * HQ / 2;

    // launch #4 = k_dftf layer 0 (ncu lands on launch #4)
    k_tab<<<(MQ * SQ + 255) / 256, 256>>>();
    k_init<<<(hPairs + 255) / 256, 256>>>(x, in_w, in_b);
    k_cvt<<<(convWPairs + 255) / 256, 256>>>(conv_w, w0p, w1p, convWPairs);
    k_dftf<<<dim3(BQ * 4, SPLITS), 128>>>();
    k_dftred<<<(BQ * MQ * HQ + 255) / 256, 256>>>();
    k_spec<<<dim3(MQ, HQ / 128), 128>>>(fw_r, fw_i);
    k_gemm_tc2<<<dim3(BQ * SQ / 128, HQ / 64), 256, dynSmem>>>(
        a0p, a1p, w0p, w1p, yp, BQ * SQ, HQ, HQ,
        (const float*)0, 0, (unsigned int*)0, (unsigned int*)0);
    k_cvt<<<(op1WPairs + 255) / 256, 256>>>(op1_w, w0p + op1WOff, w1p + op1WOff, op1WPairs);
    k_cvt<<<(op2WPairs + 255) / 256, 256>>>(op2_w, w0p + op2WOff, w1p + op2WOff, op2WPairs);
    k_idftln<<<dim3(SQ / 64, BQ), 512>>>(conv_b, ln_g, ln_b);

    for (int l = 1; l < LQ; l++) {
        k_dftf<<<dim3(BQ * 4, SPLITS), 128>>>();
        k_dftred<<<(BQ * MQ * HQ + 255) / 256, 256>>>();
        k_spec<<<dim3(MQ, HQ / 128), 128>>>(fw_r + (size_t)l * MQ * HQ * HQ,
                                            fw_i + (size_t)l * MQ * HQ * HQ);
        k_gemm_tc2<<<dim3(BQ * SQ / 128, HQ / 64), 256, dynSmem>>>(
            a0p, a1p, w0p + (size_t)l * HQ * HQ / 2, w1p + (size_t)l * HQ * HQ / 2,
            yp, BQ * SQ, HQ, HQ, (const float*)0, 0, (unsigned int*)0, (unsigned int*)0);
        k_idftln<<<dim3(SQ / 64, BQ), 512>>>(conv_b + l * HQ, ln_g + l * HQ, ln_b + l * HQ);
    }

    // output projection: H -> H/2 -> H/4 -> 1
    k_gemm_tc2<<<dim3(BQ * SQ / 128, (HQ / 2) / 64), 256, dynSmem>>>(
        a0p, a1p, w0p + op1WOff, w1p + op1WOff, yp, BQ * SQ, HQ / 2, HQ,
        op1_b, 3, o10p, o11p);
    k_gemm_tc2<<<dim3(BQ * SQ / 128, (HQ / 4) / 64), 256, dynSmem>>>(
        o10p, o11p, w0p + op2WOff, w1p + op2WOff, o2p, BQ * SQ, HQ / 4, HQ / 2,
        op2_b, 1, (unsigned int*)0, (unsigned int*)0);
    k_op3<<<BQ * SQ / 4, 128>>>(op3_w, op3_b, out);

    // cryptanalytic head
    k_mean1<<<dim3(BQ * 4, 16), 128>>>();
    k_mean2<<<(BQ * HQ + 255) / 256, 256>>>();
    k_head1<<<dim3(BQ, HQ / 128), 128>>>(h1_w, h1_b);
    k_head2<<<dim3(BQ, KBQ / 128), 128>>>(h2_w, h2_b, out);
}